// round 1
// baseline (speedup 1.0000x reference)
#include <cuda_runtime.h>
#include <cstdint>

#define Dm 32
#define Hm 64
#define NMAX 50000
#define EMAX 800000
#define BMAX 16

// ---------------- scratch (static device allocations; no cudaMalloc) -------
__device__ float g_A  [NMAX * Hm];   // per-node precomputed W1a^T x   (edge MLP)
__device__ float g_Bp [NMAX * Hm];   // per-node precomputed W1b^T x   (edge MLP)
__device__ float g_agg[NMAX * Dm];   // segment-sum of e -> dst
__device__ float g_hU [BMAX * Hm];   // per-batch: edge_b1 + W1d^T u
__device__ float g_hUn[BMAX * Hm];   // per-batch: node_b1 + W1u^T u
__device__ float g_xg [BMAX * Dm];   // segment-sum of x -> batch
__device__ float g_deg  [NMAX];
__device__ float g_rdeg [NMAX];
__device__ float g_gcnt [BMAX];
__device__ float g_rgcnt[BMAX];

// ---------------- packed f32x2 helpers (Blackwell FFMA2 path) --------------
static __device__ __forceinline__ uint64_t ffma2(uint64_t a, uint64_t b, uint64_t c) {
    uint64_t d; asm("fma.rn.f32x2 %0, %1, %2, %3;" : "=l"(d) : "l"(a), "l"(b), "l"(c));
    return d;
}
static __device__ __forceinline__ uint64_t fadd2(uint64_t a, uint64_t b) {
    uint64_t d; asm("add.rn.f32x2 %0, %1, %2;" : "=l"(d) : "l"(a), "l"(b));
    return d;
}
static __device__ __forceinline__ uint64_t pack2(float lo, float hi) {
    uint64_t r; asm("mov.b64 %0, {%1, %2};" : "=l"(r) : "f"(lo), "f"(hi));
    return r;
}
static __device__ __forceinline__ float2 unpack2(uint64_t v) {
    float lo, hi; asm("mov.b64 {%0, %1}, %2;" : "=f"(lo), "=f"(hi) : "l"(v));
    float2 f; f.x = lo; f.y = hi; return f;
}

// ---------------- init kernels ---------------------------------------------
__global__ void k_zero_counts(int N, int B) {
    int i = blockIdx.x * blockDim.x + threadIdx.x;
    if (i < N) g_deg[i] = 0.0f;
    if (i < B) g_gcnt[i] = 0.0f;
}
__global__ void k_count_deg(const int* __restrict__ dst, int E) {
    int i = blockIdx.x * blockDim.x + threadIdx.x;
    if (i < E) atomicAdd(&g_deg[dst[i]], 1.0f);
}
__global__ void k_count_batch(const int* __restrict__ batch, int N) {
    int i = blockIdx.x * blockDim.x + threadIdx.x;
    if (i < N) atomicAdd(&g_gcnt[batch[i]], 1.0f);
}
__global__ void k_recip(int N, int B) {
    int i = blockIdx.x * blockDim.x + threadIdx.x;
    if (i < N) g_rdeg[i]  = 1.0f / fmaxf(g_deg[i], 1.0f);
    if (i < B) g_rgcnt[i] = 1.0f / fmaxf(g_gcnt[i], 1.0f);
}

// eval-mode batchnorm: y = x * gamma/sqrt(1+eps) + beta  (channels = 32)
__global__ void k_bn(const float4* __restrict__ in, float4* __restrict__ out,
                     const float* __restrict__ gamma, const float* __restrict__ beta, int n4) {
    int i = blockIdx.x * blockDim.x + threadIdx.x;
    if (i >= n4) return;
    float4 v = in[i];
    int c = (i * 4) & (Dm - 1);
    const float r = rsqrtf(1.0f + 1e-5f);
    v.x = v.x * (gamma[c + 0] * r) + beta[c + 0];
    v.y = v.y * (gamma[c + 1] * r) + beta[c + 1];
    v.z = v.z * (gamma[c + 2] * r) + beta[c + 2];
    v.w = v.w * (gamma[c + 3] * r) + beta[c + 3];
    out[i] = v;
}

// ---------------- per-layer: node-term precompute for edge MLP -------------
// A[n][j] = sum_k x[n][k] * W1[k][j]        (rows 0..31  of edge_W1)
// B[n][j] = sum_k x[n][k] * W1[32+k][j]     (rows 32..63 of edge_W1)
// also zeroes g_agg for the upcoming edge kernel.
__global__ void __launch_bounds__(256) k_pre(const float* __restrict__ x,
                                             const float* __restrict__ W1, int N) {
    __shared__ float sW[2 * Dm * Hm];   // 4096 floats: rows 0..63
    int t = threadIdx.x;
    for (int i = t; i < 2 * Dm * Hm; i += 256) sW[i] = W1[i];
    __syncthreads();
    int n = blockIdx.x * 256 + t;
    if (n >= N) return;

    float4 z = make_float4(0.f, 0.f, 0.f, 0.f);
    float4* pag = (float4*)(g_agg + (size_t)n * Dm);
#pragma unroll
    for (int i = 0; i < 8; i++) pag[i] = z;

    float xr[Dm];
    const float4* px = (const float4*)(x + (size_t)n * Dm);
#pragma unroll
    for (int i = 0; i < 8; i++) {
        float4 v = px[i];
        xr[4 * i] = v.x; xr[4 * i + 1] = v.y; xr[4 * i + 2] = v.z; xr[4 * i + 3] = v.w;
    }

#pragma unroll
    for (int half = 0; half < 2; half++) {
        uint64_t a[16], b[16];
#pragma unroll
        for (int p = 0; p < 16; p++) { a[p] = 0ull; b[p] = 0ull; }
#pragma unroll 4
        for (int k = 0; k < Dm; k++) {
            uint64_t xk = pack2(xr[k], xr[k]);
            const ulonglong2* rA = (const ulonglong2*)(sW + k * Hm + half * 32);
            const ulonglong2* rB = (const ulonglong2*)(sW + (Dm + k) * Hm + half * 32);
#pragma unroll
            for (int p = 0; p < 8; p++) {
                ulonglong2 wa = rA[p];
                a[2 * p]     = ffma2(xk, wa.x, a[2 * p]);
                a[2 * p + 1] = ffma2(xk, wa.y, a[2 * p + 1]);
                ulonglong2 wb = rB[p];
                b[2 * p]     = ffma2(xk, wb.x, b[2 * p]);
                b[2 * p + 1] = ffma2(xk, wb.y, b[2 * p + 1]);
            }
        }
        uint64_t* oA = (uint64_t*)(g_A  + (size_t)n * Hm + half * 32);
        uint64_t* oB = (uint64_t*)(g_Bp + (size_t)n * Hm + half * 32);
#pragma unroll
        for (int p = 0; p < 16; p++) { oA[p] = a[p]; oB[p] = b[p]; }
    }
}

// ---------------- per-layer: per-batch u-terms; zero xg --------------------
__global__ void k_hu(const float* __restrict__ u,
                     const float* __restrict__ eW1, const float* __restrict__ eb1,
                     const float* __restrict__ nW1, const float* __restrict__ nb1, int B) {
    int j = threadIdx.x;                       // 64 threads
    for (int i = j; i < BMAX * Dm; i += Hm) g_xg[i] = 0.0f;
    for (int b = 0; b < B; b++) {
        float hu  = eb1[j];
        float hun = nb1[j];
#pragma unroll 4
        for (int k = 0; k < Dm; k++) {
            float uv = u[b * Dm + k];
            hu  += uv * eW1[(3 * Dm + k) * Hm + j];   // edge_W1 rows 96..127
            hun += uv * nW1[(2 * Dm + k) * Hm + j];   // node_W1 rows 64..95
        }
        g_hU [b * Hm + j] = hu;
        g_hUn[b * Hm + j] = hun;
    }
}

// ---------------- per-layer: edge MLP (fused scatter-sum into agg) ---------
__global__ void __launch_bounds__(256) k_edge(
    const int* __restrict__ src, const int* __restrict__ dst, const int* __restrict__ batch,
    float* __restrict__ e,
    const float* __restrict__ W1c, const float* __restrict__ W2, const float* __restrict__ b2,
    int E)
{
    __shared__ float sW1[Dm * Hm];    // edge_W1 rows 64..95 (e part)
    __shared__ float sW2[Hm * Dm];
    __shared__ float sHU[BMAX * Hm];
    __shared__ float sB2[Dm];
    int t = threadIdx.x;
    for (int i = t; i < Dm * Hm; i += 256) sW1[i] = W1c[i];
    for (int i = t; i < Hm * Dm; i += 256) sW2[i] = W2[i];
    for (int i = t; i < BMAX * Hm; i += 256) sHU[i] = g_hU[i];
    if (t < Dm) sB2[t] = b2[t];
    __syncthreads();
    int idx = blockIdx.x * 256 + t;
    if (idx >= E) return;

    int s = src[idx], d = dst[idx], b = batch[s];

    float er[Dm];
    {
        const float4* pe = (const float4*)(e + (size_t)idx * Dm);
#pragma unroll
        for (int i = 0; i < 8; i++) {
            float4 v = pe[i];
            er[4 * i] = v.x; er[4 * i + 1] = v.y; er[4 * i + 2] = v.z; er[4 * i + 3] = v.w;
        }
    }
    uint64_t out[16];
    {
        const uint64_t* pb = (const uint64_t*)sB2;
#pragma unroll
        for (int p = 0; p < 16; p++) out[p] = pb[p];
    }
    const uint64_t* pA = (const uint64_t*)(g_A  + (size_t)s * Hm);
    const uint64_t* pB = (const uint64_t*)(g_Bp + (size_t)d * Hm);
    const uint64_t* pU = (const uint64_t*)(sHU + b * Hm);

#pragma unroll
    for (int half = 0; half < 2; half++) {
        uint64_t h[16];
#pragma unroll
        for (int p = 0; p < 16; p++)
            h[p] = fadd2(fadd2(pA[half * 16 + p], pB[half * 16 + p]), pU[half * 16 + p]);
#pragma unroll 4
        for (int k = 0; k < Dm; k++) {
            uint64_t ek = pack2(er[k], er[k]);
            const ulonglong2* row = (const ulonglong2*)(sW1 + k * Hm + half * 32);
#pragma unroll
            for (int p = 0; p < 8; p++) {
                ulonglong2 w = row[p];
                h[2 * p]     = ffma2(ek, w.x, h[2 * p]);
                h[2 * p + 1] = ffma2(ek, w.y, h[2 * p + 1]);
            }
        }
        // relu + second layer (64 -> 32)
#pragma unroll
        for (int p = 0; p < 16; p++) {
            float2 hv = unpack2(h[p]);
            float h0 = fmaxf(hv.x, 0.f), h1 = fmaxf(hv.y, 0.f);
            int j0 = half * 32 + 2 * p;
            uint64_t h02 = pack2(h0, h0), h12 = pack2(h1, h1);
            const ulonglong2* r0 = (const ulonglong2*)(sW2 + j0 * Dm);
            const ulonglong2* r1 = (const ulonglong2*)(sW2 + (j0 + 1) * Dm);
#pragma unroll
            for (int q = 0; q < 8; q++) {
                ulonglong2 w0 = r0[q];
                out[2 * q]     = ffma2(h02, w0.x, out[2 * q]);
                out[2 * q + 1] = ffma2(h02, w0.y, out[2 * q + 1]);
                ulonglong2 w1 = r1[q];
                out[2 * q]     = ffma2(h12, w1.x, out[2 * q]);
                out[2 * q + 1] = ffma2(h12, w1.y, out[2 * q + 1]);
            }
        }
    }
    uint64_t* eo = (uint64_t*)(e + (size_t)idx * Dm);
    float* ag = g_agg + (size_t)d * Dm;
#pragma unroll
    for (int p = 0; p < 16; p++) {
        eo[p] = out[p];
        float2 v = unpack2(out[p]);
        atomicAdd(ag + 2 * p,     v.x);
        atomicAdd(ag + 2 * p + 1, v.y);
    }
}

// ---------------- per-layer: node MLP (fused scatter-sum into xg) ----------
__global__ void __launch_bounds__(256) k_node(
    float* __restrict__ x, const int* __restrict__ batch,
    const float* __restrict__ W1, const float* __restrict__ W2, const float* __restrict__ b2,
    int N)
{
    __shared__ float sW1[2 * Dm * Hm];  // node_W1 rows 0..63 (x part, agg part)
    __shared__ float sW2[Hm * Dm];
    __shared__ float sHU[BMAX * Hm];
    __shared__ float sB2[Dm];
    int t = threadIdx.x;
    for (int i = t; i < 2 * Dm * Hm; i += 256) sW1[i] = W1[i];
    for (int i = t; i < Hm * Dm; i += 256) sW2[i] = W2[i];
    for (int i = t; i < BMAX * Hm; i += 256) sHU[i] = g_hUn[i];
    if (t < Dm) sB2[t] = b2[t];
    __syncthreads();
    int n = blockIdx.x * 256 + t;
    if (n >= N) return;

    int b = batch[n];
    float xin[2 * Dm];
    {
        const float4* px = (const float4*)(x + (size_t)n * Dm);
#pragma unroll
        for (int i = 0; i < 8; i++) {
            float4 v = px[i];
            xin[4 * i] = v.x; xin[4 * i + 1] = v.y; xin[4 * i + 2] = v.z; xin[4 * i + 3] = v.w;
        }
        float rd = g_rdeg[n];
        const float4* pa = (const float4*)(g_agg + (size_t)n * Dm);
#pragma unroll
        for (int i = 0; i < 8; i++) {
            float4 v = pa[i];
            xin[32 + 4 * i] = v.x * rd; xin[32 + 4 * i + 1] = v.y * rd;
            xin[32 + 4 * i + 2] = v.z * rd; xin[32 + 4 * i + 3] = v.w * rd;
        }
    }
    uint64_t out[16];
    {
        const uint64_t* pb = (const uint64_t*)sB2;
#pragma unroll
        for (int p = 0; p < 16; p++) out[p] = pb[p];
    }
    const uint64_t* pU = (const uint64_t*)(sHU + b * Hm);

#pragma unroll
    for (int half = 0; half < 2; half++) {
        uint64_t h[16];
#pragma unroll
        for (int p = 0; p < 16; p++) h[p] = pU[half * 16 + p];
#pragma unroll 4
        for (int k = 0; k < 2 * Dm; k++) {
            uint64_t xk = pack2(xin[k], xin[k]);
            const ulonglong2* row = (const ulonglong2*)(sW1 + k * Hm + half * 32);
#pragma unroll
            for (int p = 0; p < 8; p++) {
                ulonglong2 w = row[p];
                h[2 * p]     = ffma2(xk, w.x, h[2 * p]);
                h[2 * p + 1] = ffma2(xk, w.y, h[2 * p + 1]);
            }
        }
#pragma unroll
        for (int p = 0; p < 16; p++) {
            float2 hv = unpack2(h[p]);
            float h0 = fmaxf(hv.x, 0.f), h1 = fmaxf(hv.y, 0.f);
            int j0 = half * 32 + 2 * p;
            uint64_t h02 = pack2(h0, h0), h12 = pack2(h1, h1);
            const ulonglong2* r0 = (const ulonglong2*)(sW2 + j0 * Dm);
            const ulonglong2* r1 = (const ulonglong2*)(sW2 + (j0 + 1) * Dm);
#pragma unroll
            for (int q = 0; q < 8; q++) {
                ulonglong2 w0 = r0[q];
                out[2 * q]     = ffma2(h02, w0.x, out[2 * q]);
                out[2 * q + 1] = ffma2(h02, w0.y, out[2 * q + 1]);
                ulonglong2 w1 = r1[q];
                out[2 * q]     = ffma2(h12, w1.x, out[2 * q]);
                out[2 * q + 1] = ffma2(h12, w1.y, out[2 * q + 1]);
            }
        }
    }
    uint64_t* xo = (uint64_t*)(x + (size_t)n * Dm);
    float* xg = g_xg + b * Dm;
#pragma unroll
    for (int p = 0; p < 16; p++) {
        xo[p] = out[p];
        float2 v = unpack2(out[p]);
        atomicAdd(xg + 2 * p,     v.x);
        atomicAdd(xg + 2 * p + 1, v.y);
    }
}

// ---------------- per-layer: global MLP ------------------------------------
__global__ void k_glob(float* __restrict__ u,
                       const float* __restrict__ W1, const float* __restrict__ b1,
                       const float* __restrict__ W2, const float* __restrict__ b2, int B) {
    __shared__ float su[BMAX * 2 * Dm];   // [u, xg_mean]
    __shared__ float sh[BMAX * Hm];
    int t = threadIdx.x;                  // 64 threads
    for (int i = t; i < B * 2 * Dm; i += Hm) {
        int bb = i / (2 * Dm), c = i % (2 * Dm);
        su[i] = (c < Dm) ? u[bb * Dm + c] : g_xg[bb * Dm + (c - Dm)] * g_rgcnt[bb];
    }
    __syncthreads();
    int j = t;
    for (int bb = 0; bb < B; bb++) {
        float h = b1[j];
#pragma unroll 4
        for (int k = 0; k < 2 * Dm; k++) h += su[bb * 2 * Dm + k] * W1[k * Hm + j];
        sh[bb * Hm + j] = fmaxf(h, 0.f);
    }
    __syncthreads();
    if (t < Dm) {
        for (int bb = 0; bb < B; bb++) {
            float o = b2[t];
#pragma unroll 4
            for (int k = 0; k < Hm; k++) o += sh[bb * Hm + k] * W2[k * Dm + t];
            u[bb * Dm + t] = o;
        }
    }
}

// ---------------- launch ----------------------------------------------------
extern "C" void kernel_launch(void* const* d_in, const int* in_sizes, int n_in,
                              void* d_out, int out_size) {
    const float* node_feats = (const float*)d_in[0];
    const int*   edge_index = (const int*)  d_in[1];
    const float* edge_feats = (const float*)d_in[2];
    const float* glob_feats = (const float*)d_in[3];
    const int*   batch      = (const int*)  d_in[4];
    const float* ngam = (const float*)d_in[5];
    const float* nbet = (const float*)d_in[6];
    const float* egam = (const float*)d_in[7];
    const float* ebet = (const float*)d_in[8];
    const float* ggam = (const float*)d_in[9];
    const float* gbet = (const float*)d_in[10];
    const float* eW1 = (const float*)d_in[11];
    const float* eb1 = (const float*)d_in[12];
    const float* eW2 = (const float*)d_in[13];
    const float* eb2 = (const float*)d_in[14];
    const float* nW1 = (const float*)d_in[15];
    const float* nb1 = (const float*)d_in[16];
    const float* nW2 = (const float*)d_in[17];
    const float* nb2 = (const float*)d_in[18];
    const float* gW1 = (const float*)d_in[19];
    const float* gb1 = (const float*)d_in[20];
    const float* gW2 = (const float*)d_in[21];
    const float* gb2 = (const float*)d_in[22];

    const int N = in_sizes[0] / Dm;
    const int E = in_sizes[2] / Dm;
    const int B = in_sizes[3] / Dm;

    float* x = (float*)d_out;
    float* e = x + (size_t)N * Dm;
    float* u = e + (size_t)E * Dm;
    const int* src = edge_index;
    const int* dst = edge_index + E;

    const int TB = 256;
    int gN  = (N + TB - 1) / TB;
    int gE  = (E + TB - 1) / TB;
    int gNx = (N * Dm / 4 + TB - 1) / TB;
    int gEx = (E * Dm / 4 + TB - 1) / TB;

    k_zero_counts<<<gN, TB>>>(N, B);
    k_count_deg  <<<gE, TB>>>(dst, E);
    k_count_batch<<<gN, TB>>>(batch, N);
    k_recip      <<<gN, TB>>>(N, B);
    k_bn<<<gNx, TB>>>((const float4*)node_feats, (float4*)x, ngam, nbet, N * Dm / 4);
    k_bn<<<gEx, TB>>>((const float4*)edge_feats, (float4*)e, egam, ebet, E * Dm / 4);
    k_bn<<<1,   TB>>>((const float4*)glob_feats, (float4*)u, ggam, gbet, B * Dm / 4);

    for (int l = 0; l < 3; l++) {
        const float* eW1l = eW1 + (size_t)l * 4 * Dm * Hm;   // (128,64)
        const float* nW1l = nW1 + (size_t)l * 3 * Dm * Hm;   // (96,64)
        const float* gW1l = gW1 + (size_t)l * 2 * Dm * Hm;   // (64,64)
        k_pre <<<gN, TB>>>(x, eW1l, N);
        k_hu  <<<1, Hm>>>(u, eW1l, eb1 + l * Hm, nW1l, nb1 + l * Hm, B);
        k_edge<<<gE, TB>>>(src, dst, batch, e,
                           eW1l + 2 * Dm * Hm,              // rows 64..95 (e part)
                           eW2 + (size_t)l * Hm * Dm, eb2 + l * Dm, E);
        k_node<<<gN, TB>>>(x, batch, nW1l,
                           nW2 + (size_t)l * Hm * Dm, nb2 + l * Dm, N);
        k_glob<<<1, Hm>>>(u, gW1l, gb1 + l * Hm,
                          gW2 + (size_t)l * Hm * Dm, gb2 + l * Dm, B);
    }
}

// round 2
// speedup vs baseline: 2.1653x; 2.1653x over previous
#include <cuda_runtime.h>
#include <cstdint>

#define Dm 32
#define Hm 64
#define NMAX 50000
#define BMAX 16

// ---------------- scratch (static device allocations) ----------------------
__device__ __align__(16) float g_A  [NMAX * Hm];
__device__ __align__(16) float g_Bp [NMAX * Hm];
__device__ __align__(16) float g_agg[NMAX * Dm];
__device__ __align__(16) float g_hU [BMAX * Hm];
__device__ __align__(16) float g_hUn[BMAX * Hm];
__device__ float g_deg [NMAX];
__device__ float g_rdeg[NMAX];

// ---------------- packed f32x2 helpers --------------------------------------
static __device__ __forceinline__ uint64_t ffma2(uint64_t a, uint64_t b, uint64_t c) {
    uint64_t d; asm("fma.rn.f32x2 %0, %1, %2, %3;" : "=l"(d) : "l"(a), "l"(b), "l"(c));
    return d;
}
static __device__ __forceinline__ uint64_t fadd2(uint64_t a, uint64_t b) {
    uint64_t d; asm("add.rn.f32x2 %0, %1, %2;" : "=l"(d) : "l"(a), "l"(b));
    return d;
}
static __device__ __forceinline__ uint64_t pack2(float lo, float hi) {
    uint64_t r; asm("mov.b64 %0, {%1, %2};" : "=l"(r) : "f"(lo), "f"(hi));
    return r;
}
static __device__ __forceinline__ float2 unpack2(uint64_t v) {
    float lo, hi; asm("mov.b64 {%0, %1}, %2;" : "=f"(lo), "=f"(hi) : "l"(v));
    float2 f; f.x = lo; f.y = hi; return f;
}
static __device__ __forceinline__ void red_add_v4(float* p, float a, float b, float c, float d) {
    asm volatile("red.global.add.v4.f32 [%0], {%1, %2, %3, %4};"
                 :: "l"(p), "f"(a), "f"(b), "f"(c), "f"(d) : "memory");
}

// ---------------- fused BN (x, e, u) + zero deg ------------------------------
__global__ void k_bn_all(const float4* __restrict__ nf, const float4* __restrict__ ef,
                         const float4* __restrict__ gf,
                         float4* __restrict__ x, float4* __restrict__ e, float4* __restrict__ u,
                         const float* __restrict__ ngam, const float* __restrict__ nbet,
                         const float* __restrict__ egam, const float* __restrict__ ebet,
                         const float* __restrict__ ggam, const float* __restrict__ gbet,
                         int N, int E, int B, int EB, int XB) {
    const float r = rsqrtf(1.0f + 1e-5f);
    int bid = blockIdx.x, t = threadIdx.x;
    const float4* in; float4* out; const float* gm; const float* bt; int i4, lim;
    if (bid < EB)            { i4 = bid * 256 + t;        lim = E * 8; in = ef; out = e; gm = egam; bt = ebet; }
    else if (bid < EB + XB)  { i4 = (bid - EB) * 256 + t; lim = N * 8; in = nf; out = x; gm = ngam; bt = nbet;
                               if (i4 < N) g_deg[i4] = 0.0f; }
    else                     { i4 = t;                    lim = B * 8; in = gf; out = u; gm = ggam; bt = gbet; }
    if (i4 >= lim) return;
    float4 v = in[i4];
    int c = (i4 * 4) & (Dm - 1);
    v.x = v.x * (gm[c + 0] * r) + bt[c + 0];
    v.y = v.y * (gm[c + 1] * r) + bt[c + 1];
    v.z = v.z * (gm[c + 2] * r) + bt[c + 2];
    v.w = v.w * (gm[c + 3] * r) + bt[c + 3];
    out[i4] = v;
}

__global__ void k_count_deg(const int* __restrict__ dst, int E) {
    int i = blockIdx.x * blockDim.x + threadIdx.x;
    if (i < E) atomicAdd(&g_deg[dst[i]], 1.0f);
}

// ---------------- per-layer: A/B precompute + rdeg + zero agg; last block: hU
__global__ void __launch_bounds__(256) k_pre_hu(const float* __restrict__ x,
                                                const float* __restrict__ u,
                                                const float* __restrict__ eW1, const float* __restrict__ eb1,
                                                const float* __restrict__ nW1, const float* __restrict__ nb1,
                                                int N, int B) {
    int t = threadIdx.x;
    if (blockIdx.x == gridDim.x - 1) {
        if (t < Hm) {
            int j = t;
            for (int b = 0; b < B; b++) {
                float hu = eb1[j], hun = nb1[j];
#pragma unroll 4
                for (int k = 0; k < Dm; k++) {
                    float uv = u[b * Dm + k];
                    hu  += uv * eW1[(3 * Dm + k) * Hm + j];
                    hun += uv * nW1[(2 * Dm + k) * Hm + j];
                }
                g_hU [b * Hm + j] = hu;
                g_hUn[b * Hm + j] = hun;
            }
        }
        return;
    }
    __shared__ __align__(16) float sW[2 * Dm * Hm];
    for (int i = t; i < 2 * Dm * Hm; i += 256) sW[i] = eW1[i];
    __syncthreads();
    int n = blockIdx.x * 256 + t;
    if (n >= N) return;

    g_rdeg[n] = 1.0f / fmaxf(g_deg[n], 1.0f);
    float4 z = make_float4(0.f, 0.f, 0.f, 0.f);
    float4* pag = (float4*)(g_agg + (size_t)n * Dm);
#pragma unroll
    for (int i = 0; i < 8; i++) pag[i] = z;

    float xr[Dm];
    const float4* px = (const float4*)(x + (size_t)n * Dm);
#pragma unroll
    for (int i = 0; i < 8; i++) {
        float4 v = px[i];
        xr[4 * i] = v.x; xr[4 * i + 1] = v.y; xr[4 * i + 2] = v.z; xr[4 * i + 3] = v.w;
    }
#pragma unroll
    for (int half = 0; half < 2; half++) {
        uint64_t a[16], b[16];
#pragma unroll
        for (int p = 0; p < 16; p++) { a[p] = 0ull; b[p] = 0ull; }
#pragma unroll 4
        for (int k = 0; k < Dm; k++) {
            uint64_t xk = pack2(xr[k], xr[k]);
            const ulonglong2* rA = (const ulonglong2*)(sW + k * Hm + half * 32);
            const ulonglong2* rB = (const ulonglong2*)(sW + (Dm + k) * Hm + half * 32);
#pragma unroll
            for (int p = 0; p < 8; p++) {
                ulonglong2 wa = rA[p];
                a[2 * p]     = ffma2(xk, wa.x, a[2 * p]);
                a[2 * p + 1] = ffma2(xk, wa.y, a[2 * p + 1]);
                ulonglong2 wb = rB[p];
                b[2 * p]     = ffma2(xk, wb.x, b[2 * p]);
                b[2 * p + 1] = ffma2(xk, wb.y, b[2 * p + 1]);
            }
        }
        uint64_t* oA = (uint64_t*)(g_A  + (size_t)n * Hm + half * 32);
        uint64_t* oB = (uint64_t*)(g_Bp + (size_t)n * Hm + half * 32);
#pragma unroll
        for (int p = 0; p < 16; p++) { oA[p] = a[p]; oB[p] = b[p]; }
    }
}

// ---------------- per-layer: edge MLP (staged gathers, fused RED v4) --------
__global__ void __launch_bounds__(256, 2) k_edge(
    const int* __restrict__ src, const int* __restrict__ dst, const int* __restrict__ batch,
    float* __restrict__ e,
    const float* __restrict__ W1c, const float* __restrict__ W2, const float* __restrict__ b2,
    int E)
{
    __shared__ __align__(16) float sW1[Dm * Hm];     // 8KB: edge_W1 rows 64..95 (e part)
    __shared__ __align__(16) float sW2[Hm * Dm];     // 8KB
    __shared__ __align__(16) float sH[128 * 36];     // 18KB: staged A+B+hU half-rows
    __shared__ int sS[256], sD[256], sBt[256];
    int t = threadIdx.x;
    for (int i = t; i < Dm * Hm; i += 256) sW1[i] = W1c[i];
    for (int i = t; i < Hm * Dm; i += 256) sW2[i] = W2[i];

    int e0 = blockIdx.x * 256;
    int ei = min(e0 + t, E - 1);
    bool valid = (e0 + t) < E;
    { int s = src[ei]; sS[t] = s; sD[t] = dst[ei]; sBt[t] = batch[s]; }
    const float* eptr = e + (size_t)ei * Dm;

    uint64_t out[16];
    {
        const float4* pb = (const float4*)b2;            // L1-cached
#pragma unroll
        for (int q = 0; q < 8; q++) {
            float4 v = __ldg(pb + q);
            out[2 * q] = pack2(v.x, v.y); out[2 * q + 1] = pack2(v.z, v.w);
        }
    }
    __syncthreads();

    int lane8 = t & 7, grp = t >> 3;   // 8 lanes per edge, 32 edges per pass

#pragma unroll
    for (int half = 0; half < 2; half++) {
        uint64_t h[16];
        // ---- stage chunk 0 (edges 0..127) then chunk 1 (128..255) ----
#pragma unroll
        for (int ch = 0; ch < 2; ch++) {
#pragma unroll
            for (int pass = 0; pass < 4; pass++) {
                int eL = ch * 128 + pass * 32 + grp;
                int s = sS[eL], d = sD[eL], bb = sBt[eL];
                float4 av = __ldg((const float4*)(g_A  + (size_t)s * Hm + half * 32) + lane8);
                float4 bv = __ldg((const float4*)(g_Bp + (size_t)d * Hm + half * 32) + lane8);
                float4 hv = __ldg((const float4*)(g_hU + bb * Hm + half * 32) + lane8);
                float4 sm;
                sm.x = av.x + bv.x + hv.x; sm.y = av.y + bv.y + hv.y;
                sm.z = av.z + bv.z + hv.z; sm.w = av.w + bv.w + hv.w;
                *((float4*)(sH + (eL - ch * 128) * 36) + lane8) = sm;
            }
            __syncthreads();
            if ((t >> 7) == ch) {
                const ulonglong2* ph = (const ulonglong2*)(sH + (t & 127) * 36);
#pragma unroll
                for (int p = 0; p < 8; p++) {
                    ulonglong2 v = ph[p];
                    h[2 * p] = v.x; h[2 * p + 1] = v.y;
                }
            }
            __syncthreads();
        }
        // ---- layer 1: += W1c^T e  (k-chunked e loads) ----
#pragma unroll
        for (int kc = 0; kc < 4; kc++) {
            float4 ev0 = __ldg((const float4*)eptr + kc * 2);
            float4 ev1 = __ldg((const float4*)eptr + kc * 2 + 1);
            float ech[8] = {ev0.x, ev0.y, ev0.z, ev0.w, ev1.x, ev1.y, ev1.z, ev1.w};
#pragma unroll
            for (int k8 = 0; k8 < 8; k8++) {
                int k = kc * 8 + k8;
                uint64_t ek = pack2(ech[k8], ech[k8]);
                const ulonglong2* wr = (const ulonglong2*)(sW1 + k * Hm + half * 32);
#pragma unroll
                for (int p = 0; p < 8; p++) {
                    ulonglong2 w = wr[p];
                    h[2 * p]     = ffma2(ek, w.x, h[2 * p]);
                    h[2 * p + 1] = ffma2(ek, w.y, h[2 * p + 1]);
                }
            }
        }
        // ---- relu + layer 2 accumulate into out ----
#pragma unroll
        for (int pp = 0; pp < 16; pp++) {
            float2 hv = unpack2(h[pp]);
            float h0 = fmaxf(hv.x, 0.f), h1 = fmaxf(hv.y, 0.f);
            int j0 = half * 32 + 2 * pp;
            uint64_t h02 = pack2(h0, h0), h12 = pack2(h1, h1);
            const ulonglong2* r0 = (const ulonglong2*)(sW2 + j0 * Dm);
            const ulonglong2* r1 = (const ulonglong2*)(sW2 + (j0 + 1) * Dm);
#pragma unroll
            for (int q = 0; q < 8; q++) {
                ulonglong2 w0 = r0[q];
                out[2 * q]     = ffma2(h02, w0.x, out[2 * q]);
                out[2 * q + 1] = ffma2(h02, w0.y, out[2 * q + 1]);
                ulonglong2 w1 = r1[q];
                out[2 * q]     = ffma2(h12, w1.x, out[2 * q]);
                out[2 * q + 1] = ffma2(h12, w1.y, out[2 * q + 1]);
            }
        }
        __syncthreads();
    }
    if (valid) {
        ulonglong2* eo = (ulonglong2*)(e + (size_t)ei * Dm);
        float* ag = g_agg + (size_t)sD[t] * Dm;
#pragma unroll
        for (int q = 0; q < 8; q++) {
            ulonglong2 v; v.x = out[2 * q]; v.y = out[2 * q + 1];
            eo[q] = v;
            float2 v0 = unpack2(out[2 * q]); float2 v1 = unpack2(out[2 * q + 1]);
            red_add_v4(ag + 4 * q, v0.x, v0.y, v1.x, v1.y);
        }
    }
}

// ---------------- per-layer: node MLP ---------------------------------------
__global__ void __launch_bounds__(256, 2) k_node(
    float* __restrict__ x, const int* __restrict__ batch,
    const float* __restrict__ W1, const float* __restrict__ W2, const float* __restrict__ b2,
    int N)
{
    __shared__ __align__(16) float sW1[2 * Dm * Hm];  // 16KB rows 0..63 (x, agg)
    __shared__ __align__(16) float sW2[Hm * Dm];      // 8KB
    __shared__ __align__(16) float sHU[BMAX * Hm];    // 4KB
    int t = threadIdx.x;
    for (int i = t; i < 2 * Dm * Hm; i += 256) sW1[i] = W1[i];
    for (int i = t; i < Hm * Dm; i += 256) sW2[i] = W2[i];
    for (int i = t; i < BMAX * Hm; i += 256) sHU[i] = g_hUn[i];
    __syncthreads();
    int n = blockIdx.x * 256 + t;
    if (n >= N) return;

    int b = batch[n];
    float rd = g_rdeg[n];
    const float* xptr = x + (size_t)n * Dm;
    const float* aptr = g_agg + (size_t)n * Dm;

    uint64_t out[16];
    {
        const float4* pb = (const float4*)b2;
#pragma unroll
        for (int q = 0; q < 8; q++) {
            float4 v = __ldg(pb + q);
            out[2 * q] = pack2(v.x, v.y); out[2 * q + 1] = pack2(v.z, v.w);
        }
    }
#pragma unroll
    for (int half = 0; half < 2; half++) {
        uint64_t h[16];
        const ulonglong2* pu = (const ulonglong2*)(sHU + b * Hm + half * 32);
#pragma unroll
        for (int p = 0; p < 8; p++) { ulonglong2 v = pu[p]; h[2 * p] = v.x; h[2 * p + 1] = v.y; }
#pragma unroll
        for (int kc = 0; kc < 8; kc++) {
            float4 ev0, ev1;
            if (kc < 4) { ev0 = __ldg((const float4*)xptr + kc * 2);
                          ev1 = __ldg((const float4*)xptr + kc * 2 + 1); }
            else {
                float4 a0 = __ldg((const float4*)aptr + (kc - 4) * 2);
                float4 a1 = __ldg((const float4*)aptr + (kc - 4) * 2 + 1);
                ev0.x = a0.x * rd; ev0.y = a0.y * rd; ev0.z = a0.z * rd; ev0.w = a0.w * rd;
                ev1.x = a1.x * rd; ev1.y = a1.y * rd; ev1.z = a1.z * rd; ev1.w = a1.w * rd;
            }
            float ech[8] = {ev0.x, ev0.y, ev0.z, ev0.w, ev1.x, ev1.y, ev1.z, ev1.w};
#pragma unroll
            for (int k8 = 0; k8 < 8; k8++) {
                int k = kc * 8 + k8;
                uint64_t ek = pack2(ech[k8], ech[k8]);
                const ulonglong2* wr = (const ulonglong2*)(sW1 + k * Hm + half * 32);
#pragma unroll
                for (int p = 0; p < 8; p++) {
                    ulonglong2 w = wr[p];
                    h[2 * p]     = ffma2(ek, w.x, h[2 * p]);
                    h[2 * p + 1] = ffma2(ek, w.y, h[2 * p + 1]);
                }
            }
        }
#pragma unroll
        for (int pp = 0; pp < 16; pp++) {
            float2 hv = unpack2(h[pp]);
            float h0 = fmaxf(hv.x, 0.f), h1 = fmaxf(hv.y, 0.f);
            int j0 = half * 32 + 2 * pp;
            uint64_t h02 = pack2(h0, h0), h12 = pack2(h1, h1);
            const ulonglong2* r0 = (const ulonglong2*)(sW2 + j0 * Dm);
            const ulonglong2* r1 = (const ulonglong2*)(sW2 + (j0 + 1) * Dm);
#pragma unroll
            for (int q = 0; q < 8; q++) {
                ulonglong2 w0 = r0[q];
                out[2 * q]     = ffma2(h02, w0.x, out[2 * q]);
                out[2 * q + 1] = ffma2(h02, w0.y, out[2 * q + 1]);
                ulonglong2 w1 = r1[q];
                out[2 * q]     = ffma2(h12, w1.x, out[2 * q]);
                out[2 * q + 1] = ffma2(h12, w1.y, out[2 * q + 1]);
            }
        }
    }
    ulonglong2* xo = (ulonglong2*)(x + (size_t)n * Dm);
#pragma unroll
    for (int q = 0; q < 8; q++) { ulonglong2 v; v.x = out[2 * q]; v.y = out[2 * q + 1]; xo[q] = v; }
}

// ---------------- per-layer: global MLP (sorted-batch segment reduce) -------
static __device__ __forceinline__ int lowerb(const int* __restrict__ a, int n, int v) {
    int lo = 0, hi = n;
    while (lo < hi) { int m = (lo + hi) >> 1; if (a[m] < v) lo = m + 1; else hi = m; }
    return lo;
}
__global__ void k_glob(float* __restrict__ u, const float* __restrict__ x,
                       const int* __restrict__ batch,
                       const float* __restrict__ W1, const float* __restrict__ b1,
                       const float* __restrict__ W2, const float* __restrict__ b2, int N) {
    int b = blockIdx.x, t = threadIdx.x;       // 128 threads
    __shared__ int sLo, sHi;
    if (t == 0) { sLo = lowerb(batch, N, b); sHi = lowerb(batch, N, b + 1); }
    __syncthreads();
    int lo = sLo, hi = sHi;
    float cnt = fmaxf((float)(hi - lo), 1.0f);
    int c = t & 31, g = t >> 5;
    float acc = 0.f;
    for (int r = lo + g; r < hi; r += 4) acc += x[(size_t)r * Dm + c];
    __shared__ float sred[4][Dm];
    sred[g][c] = acc;
    __syncthreads();
    __shared__ float su[2 * Dm];
    __shared__ float sh[Hm];
    if (t < Dm) su[t] = u[b * Dm + t];
    else if (t < 2 * Dm) {
        int cc = t - Dm;
        su[t] = (sred[0][cc] + sred[1][cc] + sred[2][cc] + sred[3][cc]) / cnt;
    }
    __syncthreads();
    if (t < Hm) {
        float h = b1[t];
#pragma unroll 4
        for (int k = 0; k < 2 * Dm; k++) h += su[k] * W1[k * Hm + t];
        sh[t] = fmaxf(h, 0.f);
    }
    __syncthreads();
    if (t < Dm) {
        float o = b2[t];
#pragma unroll 4
        for (int k = 0; k < Hm; k++) o += sh[k] * W2[k * Dm + t];
        u[b * Dm + t] = o;
    }
}

// ---------------- launch ----------------------------------------------------
extern "C" void kernel_launch(void* const* d_in, const int* in_sizes, int n_in,
                              void* d_out, int out_size) {
    const float* node_feats = (const float*)d_in[0];
    const int*   edge_index = (const int*)  d_in[1];
    const float* edge_feats = (const float*)d_in[2];
    const float* glob_feats = (const float*)d_in[3];
    const int*   batch      = (const int*)  d_in[4];
    const float* ngam = (const float*)d_in[5];
    const float* nbet = (const float*)d_in[6];
    const float* egam = (const float*)d_in[7];
    const float* ebet = (const float*)d_in[8];
    const float* ggam = (const float*)d_in[9];
    const float* gbet = (const float*)d_in[10];
    const float* eW1 = (const float*)d_in[11];
    const float* eb1 = (const float*)d_in[12];
    const float* eW2 = (const float*)d_in[13];
    const float* eb2 = (const float*)d_in[14];
    const float* nW1 = (const float*)d_in[15];
    const float* nb1 = (const float*)d_in[16];
    const float* nW2 = (const float*)d_in[17];
    const float* nb2 = (const float*)d_in[18];
    const float* gW1 = (const float*)d_in[19];
    const float* gb1 = (const float*)d_in[20];
    const float* gW2 = (const float*)d_in[21];
    const float* gb2 = (const float*)d_in[22];

    const int N = in_sizes[0] / Dm;
    const int E = in_sizes[2] / Dm;
    const int B = in_sizes[3] / Dm;

    float* x = (float*)d_out;
    float* e = x + (size_t)N * Dm;
    float* u = e + (size_t)E * Dm;
    const int* src = edge_index;
    const int* dst = edge_index + E;

    const int TB = 256;
    int EB = (E * 8 + TB - 1) / TB;
    int XB = (N * 8 + TB - 1) / TB;
    int gE = (E + TB - 1) / TB;
    int gN = (N + TB - 1) / TB;

    // launch 0: fused BN + zero deg
    k_bn_all<<<EB + XB + 1, TB>>>((const float4*)node_feats, (const float4*)edge_feats,
                                  (const float4*)glob_feats,
                                  (float4*)x, (float4*)e, (float4*)u,
                                  ngam, nbet, egam, ebet, ggam, gbet, N, E, B, EB, XB);
    // launch 1: degree count
    k_count_deg<<<gE, TB>>>(dst, E);

    for (int l = 0; l < 3; l++) {
        const float* eW1l = eW1 + (size_t)l * 4 * Dm * Hm;
        const float* nW1l = nW1 + (size_t)l * 3 * Dm * Hm;
        const float* gW1l = gW1 + (size_t)l * 2 * Dm * Hm;
        k_pre_hu<<<gN + 1, TB>>>(x, u, eW1l, eb1 + l * Hm, nW1l, nb1 + l * Hm, N, B);
        k_edge<<<gE, TB>>>(src, dst, batch, e,
                           eW1l + 2 * Dm * Hm,
                           eW2 + (size_t)l * Hm * Dm, eb2 + l * Dm, E);
        k_node<<<gN, TB>>>(x, batch, nW1l,
                           nW2 + (size_t)l * Hm * Dm, nb2 + l * Dm, N);
        k_glob<<<B, 128>>>(u, x, batch, gW1l, gb1 + l * Hm,
                           gW2 + (size_t)l * Hm * Dm, gb2 + l * Dm, N);
    }
}

// round 3
// speedup vs baseline: 2.1912x; 1.0120x over previous
#include <cuda_runtime.h>
#include <cstdint>

#define Dm 32
#define Hm 64
#define NMAX 50000
#define BMAX 16

// ---------------- scratch (static device allocations) ----------------------
__device__ __align__(16) float g_A  [NMAX * Hm];
__device__ __align__(16) float g_Bp [NMAX * Hm];
__device__ __align__(16) float g_agg[NMAX * Dm];
__device__ __align__(16) float g_hU [BMAX * Hm];
__device__ __align__(16) float g_hUn[BMAX * Hm];
__device__ float g_deg [NMAX];
__device__ float g_rdeg[NMAX];

// ---------------- packed f32x2 helpers --------------------------------------
static __device__ __forceinline__ uint64_t ffma2(uint64_t a, uint64_t b, uint64_t c) {
    uint64_t d; asm("fma.rn.f32x2 %0, %1, %2, %3;" : "=l"(d) : "l"(a), "l"(b), "l"(c));
    return d;
}
static __device__ __forceinline__ uint64_t fadd2(uint64_t a, uint64_t b) {
    uint64_t d; asm("add.rn.f32x2 %0, %1, %2;" : "=l"(d) : "l"(a), "l"(b));
    return d;
}
static __device__ __forceinline__ uint64_t pack2(float lo, float hi) {
    uint64_t r; asm("mov.b64 %0, {%1, %2};" : "=l"(r) : "f"(lo), "f"(hi));
    return r;
}
static __device__ __forceinline__ float2 unpack2(uint64_t v) {
    float lo, hi; asm("mov.b64 {%0, %1}, %2;" : "=f"(lo), "=f"(hi) : "l"(v));
    float2 f; f.x = lo; f.y = hi; return f;
}
static __device__ __forceinline__ void red_add_v4(float* p, float a, float b, float c, float d) {
    asm volatile("red.global.add.v4.f32 [%0], {%1, %2, %3, %4};"
                 :: "l"(p), "f"(a), "f"(b), "f"(c), "f"(d) : "memory");
}

// ---------------- fused BN (x, e, u) + zero deg ------------------------------
__global__ void k_bn_all(const float4* __restrict__ nf, const float4* __restrict__ ef,
                         const float4* __restrict__ gf,
                         float4* __restrict__ x, float4* __restrict__ e, float4* __restrict__ u,
                         const float* __restrict__ ngam, const float* __restrict__ nbet,
                         const float* __restrict__ egam, const float* __restrict__ ebet,
                         const float* __restrict__ ggam, const float* __restrict__ gbet,
                         int N, int E, int B, int EB, int XB) {
    const float r = rsqrtf(1.0f + 1e-5f);
    int bid = blockIdx.x, t = threadIdx.x;
    const float4* in; float4* out; const float* gm; const float* bt; int i4, lim;
    if (bid < EB)            { i4 = bid * 256 + t;        lim = E * 8; in = ef; out = e; gm = egam; bt = ebet; }
    else if (bid < EB + XB)  { i4 = (bid - EB) * 256 + t; lim = N * 8; in = nf; out = x; gm = ngam; bt = nbet;
                               if (i4 < N) g_deg[i4] = 0.0f; }
    else                     { i4 = t;                    lim = B * 8; in = gf; out = u; gm = ggam; bt = gbet; }
    if (i4 >= lim) return;
    float4 v = in[i4];
    int c = (i4 * 4) & (Dm - 1);
    v.x = v.x * (gm[c + 0] * r) + bt[c + 0];
    v.y = v.y * (gm[c + 1] * r) + bt[c + 1];
    v.z = v.z * (gm[c + 2] * r) + bt[c + 2];
    v.w = v.w * (gm[c + 3] * r) + bt[c + 3];
    out[i4] = v;
}

__global__ void k_count_deg(const int* __restrict__ dst, int E) {
    int i = blockIdx.x * blockDim.x + threadIdx.x;
    if (i < E) atomicAdd(&g_deg[dst[i]], 1.0f);
}

// ---------------- per-layer: A/B precompute + rdeg + zero agg; last block: hU
__global__ void __launch_bounds__(256) k_pre_hu(const float* __restrict__ x,
                                                const float* __restrict__ u,
                                                const float* __restrict__ eW1, const float* __restrict__ eb1,
                                                const float* __restrict__ nW1, const float* __restrict__ nb1,
                                                int N, int B) {
    int t = threadIdx.x;
    if (blockIdx.x == gridDim.x - 1) {
        if (t < Hm) {
            int j = t;
            for (int b = 0; b < B; b++) {
                float hu = eb1[j], hun = nb1[j];
#pragma unroll 4
                for (int k = 0; k < Dm; k++) {
                    float uv = u[b * Dm + k];
                    hu  += uv * eW1[(3 * Dm + k) * Hm + j];
                    hun += uv * nW1[(2 * Dm + k) * Hm + j];
                }
                g_hU [b * Hm + j] = hu;
                g_hUn[b * Hm + j] = hun;
            }
        }
        return;
    }
    __shared__ __align__(16) float sW[2 * Dm * Hm];
    for (int i = t; i < 2 * Dm * Hm; i += 256) sW[i] = eW1[i];
    __syncthreads();
    int n = blockIdx.x * 256 + t;
    if (n >= N) return;

    g_rdeg[n] = 1.0f / fmaxf(g_deg[n], 1.0f);
    float4 z = make_float4(0.f, 0.f, 0.f, 0.f);
    float4* pag = (float4*)(g_agg + (size_t)n * Dm);
#pragma unroll
    for (int i = 0; i < 8; i++) pag[i] = z;

    float xr[Dm];
    const float4* px = (const float4*)(x + (size_t)n * Dm);
#pragma unroll
    for (int i = 0; i < 8; i++) {
        float4 v = px[i];
        xr[4 * i] = v.x; xr[4 * i + 1] = v.y; xr[4 * i + 2] = v.z; xr[4 * i + 3] = v.w;
    }
#pragma unroll
    for (int half = 0; half < 2; half++) {
        uint64_t a[16], b[16];
#pragma unroll
        for (int p = 0; p < 16; p++) { a[p] = 0ull; b[p] = 0ull; }
#pragma unroll 4
        for (int k = 0; k < Dm; k++) {
            uint64_t xk = pack2(xr[k], xr[k]);
            const ulonglong2* rA = (const ulonglong2*)(sW + k * Hm + half * 32);
            const ulonglong2* rB = (const ulonglong2*)(sW + (Dm + k) * Hm + half * 32);
#pragma unroll
            for (int p = 0; p < 8; p++) {
                ulonglong2 wa = rA[p];
                a[2 * p]     = ffma2(xk, wa.x, a[2 * p]);
                a[2 * p + 1] = ffma2(xk, wa.y, a[2 * p + 1]);
                ulonglong2 wb = rB[p];
                b[2 * p]     = ffma2(xk, wb.x, b[2 * p]);
                b[2 * p + 1] = ffma2(xk, wb.y, b[2 * p + 1]);
            }
        }
        uint64_t* oA = (uint64_t*)(g_A  + (size_t)n * Hm + half * 32);
        uint64_t* oB = (uint64_t*)(g_Bp + (size_t)n * Hm + half * 32);
#pragma unroll
        for (int p = 0; p < 16; p++) { oA[p] = a[p]; oB[p] = b[p]; }
    }
}

// ---------------- per-layer: edge MLP (staged gathers, fused RED v4) --------
__global__ void __launch_bounds__(256, 2) k_edge(
    const int* __restrict__ src, const int* __restrict__ dst, const int* __restrict__ batch,
    float* __restrict__ e,
    const float* __restrict__ W1c, const float* __restrict__ W2, const float* __restrict__ b2,
    int E)
{
    __shared__ __align__(16) float sW1[Dm * Hm];     // 8KB: edge_W1 rows 64..95 (e part)
    __shared__ __align__(16) float sW2[Hm * Dm];     // 8KB
    __shared__ __align__(16) float sH[128 * 36];     // 18KB: staged A+B+hU half-rows
    __shared__ int sS[256], sD[256], sBt[256];
    int t = threadIdx.x;
    for (int i = t; i < Dm * Hm; i += 256) sW1[i] = W1c[i];
    for (int i = t; i < Hm * Dm; i += 256) sW2[i] = W2[i];

    int e0 = blockIdx.x * 256;
    int ei = min(e0 + t, E - 1);
    bool valid = (e0 + t) < E;
    { int s = src[ei]; sS[t] = s; sD[t] = dst[ei]; sBt[t] = batch[s]; }
    const float* eptr = e + (size_t)ei * Dm;

    uint64_t out[16];
    {
        const float4* pb = (const float4*)b2;            // L1-cached
#pragma unroll
        for (int q = 0; q < 8; q++) {
            float4 v = __ldg(pb + q);
            out[2 * q] = pack2(v.x, v.y); out[2 * q + 1] = pack2(v.z, v.w);
        }
    }
    __syncthreads();

    int lane8 = t & 7, grp = t >> 3;   // 8 lanes per edge, 32 edges per pass

#pragma unroll
    for (int half = 0; half < 2; half++) {
        uint64_t h[16];
        // ---- stage chunk 0 (edges 0..127) then chunk 1 (128..255) ----
#pragma unroll
        for (int ch = 0; ch < 2; ch++) {
#pragma unroll
            for (int pass = 0; pass < 4; pass++) {
                int eL = ch * 128 + pass * 32 + grp;
                int s = sS[eL], d = sD[eL], bb = sBt[eL];
                float4 av = __ldg((const float4*)(g_A  + (size_t)s * Hm + half * 32) + lane8);
                float4 bv = __ldg((const float4*)(g_Bp + (size_t)d * Hm + half * 32) + lane8);
                float4 hv = __ldg((const float4*)(g_hU + bb * Hm + half * 32) + lane8);
                float4 sm;
                sm.x = av.x + bv.x + hv.x; sm.y = av.y + bv.y + hv.y;
                sm.z = av.z + bv.z + hv.z; sm.w = av.w + bv.w + hv.w;
                *((float4*)(sH + (eL - ch * 128) * 36) + lane8) = sm;
            }
            __syncthreads();
            if ((t >> 7) == ch) {
                const ulonglong2* ph = (const ulonglong2*)(sH + (t & 127) * 36);
#pragma unroll
                for (int p = 0; p < 8; p++) {
                    ulonglong2 v = ph[p];
                    h[2 * p] = v.x; h[2 * p + 1] = v.y;
                }
            }
            __syncthreads();
        }
        // ---- layer 1: += W1c^T e  (k-chunked e loads) ----
#pragma unroll
        for (int kc = 0; kc < 4; kc++) {
            float4 ev0 = __ldg((const float4*)eptr + kc * 2);
            float4 ev1 = __ldg((const float4*)eptr + kc * 2 + 1);
            float ech[8] = {ev0.x, ev0.y, ev0.z, ev0.w, ev1.x, ev1.y, ev1.z, ev1.w};
#pragma unroll
            for (int k8 = 0; k8 < 8; k8++) {
                int k = kc * 8 + k8;
                uint64_t ek = pack2(ech[k8], ech[k8]);
                const ulonglong2* wr = (const ulonglong2*)(sW1 + k * Hm + half * 32);
#pragma unroll
                for (int p = 0; p < 8; p++) {
                    ulonglong2 w = wr[p];
                    h[2 * p]     = ffma2(ek, w.x, h[2 * p]);
                    h[2 * p + 1] = ffma2(ek, w.y, h[2 * p + 1]);
                }
            }
        }
        // ---- relu + layer 2 accumulate into out ----
#pragma unroll
        for (int pp = 0; pp < 16; pp++) {
            float2 hv = unpack2(h[pp]);
            float h0 = fmaxf(hv.x, 0.f), h1 = fmaxf(hv.y, 0.f);
            int j0 = half * 32 + 2 * pp;
            uint64_t h02 = pack2(h0, h0), h12 = pack2(h1, h1);
            const ulonglong2* r0 = (const ulonglong2*)(sW2 + j0 * Dm);
            const ulonglong2* r1 = (const ulonglong2*)(sW2 + (j0 + 1) * Dm);
#pragma unroll
            for (int q = 0; q < 8; q++) {
                ulonglong2 w0 = r0[q];
                out[2 * q]     = ffma2(h02, w0.x, out[2 * q]);
                out[2 * q + 1] = ffma2(h02, w0.y, out[2 * q + 1]);
                ulonglong2 w1 = r1[q];
                out[2 * q]     = ffma2(h12, w1.x, out[2 * q]);
                out[2 * q + 1] = ffma2(h12, w1.y, out[2 * q + 1]);
            }
        }
        __syncthreads();
    }
    if (valid) {
        ulonglong2* eo = (ulonglong2*)(e + (size_t)ei * Dm);
        float* ag = g_agg + (size_t)sD[t] * Dm;
#pragma unroll
        for (int q = 0; q < 8; q++) {
            ulonglong2 v; v.x = out[2 * q]; v.y = out[2 * q + 1];
            eo[q] = v;
            float2 v0 = unpack2(out[2 * q]); float2 v1 = unpack2(out[2 * q + 1]);
            red_add_v4(ag + 4 * q, v0.x, v0.y, v1.x, v1.y);
        }
    }
}

// ---------------- per-layer: node MLP ---------------------------------------
__global__ void __launch_bounds__(256, 2) k_node(
    float* __restrict__ x, const int* __restrict__ batch,
    const float* __restrict__ W1, const float* __restrict__ W2, const float* __restrict__ b2,
    int N)
{
    __shared__ __align__(16) float sW1[2 * Dm * Hm];  // 16KB rows 0..63 (x, agg)
    __shared__ __align__(16) float sW2[Hm * Dm];      // 8KB
    __shared__ __align__(16) float sHU[BMAX * Hm];    // 4KB
    int t = threadIdx.x;
    for (int i = t; i < 2 * Dm * Hm; i += 256) sW1[i] = W1[i];
    for (int i = t; i < Hm * Dm; i += 256) sW2[i] = W2[i];
    for (int i = t; i < BMAX * Hm; i += 256) sHU[i] = g_hUn[i];
    __syncthreads();
    int n = blockIdx.x * 256 + t;
    if (n >= N) return;

    int b = batch[n];
    float rd = g_rdeg[n];
    const float* xptr = x + (size_t)n * Dm;
    const float* aptr = g_agg + (size_t)n * Dm;

    uint64_t out[16];
    {
        const float4* pb = (const float4*)b2;
#pragma unroll
        for (int q = 0; q < 8; q++) {
            float4 v = __ldg(pb + q);
            out[2 * q] = pack2(v.x, v.y); out[2 * q + 1] = pack2(v.z, v.w);
        }
    }
#pragma unroll
    for (int half = 0; half < 2; half++) {
        uint64_t h[16];
        const ulonglong2* pu = (const ulonglong2*)(sHU + b * Hm + half * 32);
#pragma unroll
        for (int p = 0; p < 8; p++) { ulonglong2 v = pu[p]; h[2 * p] = v.x; h[2 * p + 1] = v.y; }
#pragma unroll
        for (int kc = 0; kc < 8; kc++) {
            float4 ev0, ev1;
            if (kc < 4) { ev0 = __ldg((const float4*)xptr + kc * 2);
                          ev1 = __ldg((const float4*)xptr + kc * 2 + 1); }
            else {
                float4 a0 = __ldg((const float4*)aptr + (kc - 4) * 2);
                float4 a1 = __ldg((const float4*)aptr + (kc - 4) * 2 + 1);
                ev0.x = a0.x * rd; ev0.y = a0.y * rd; ev0.z = a0.z * rd; ev0.w = a0.w * rd;
                ev1.x = a1.x * rd; ev1.y = a1.y * rd; ev1.z = a1.z * rd; ev1.w = a1.w * rd;
            }
            float ech[8] = {ev0.x, ev0.y, ev0.z, ev0.w, ev1.x, ev1.y, ev1.z, ev1.w};
#pragma unroll
            for (int k8 = 0; k8 < 8; k8++) {
                int k = kc * 8 + k8;
                uint64_t ek = pack2(ech[k8], ech[k8]);
                const ulonglong2* wr = (const ulonglong2*)(sW1 + k * Hm + half * 32);
#pragma unroll
                for (int p = 0; p < 8; p++) {
                    ulonglong2 w = wr[p];
                    h[2 * p]     = ffma2(ek, w.x, h[2 * p]);
                    h[2 * p + 1] = ffma2(ek, w.y, h[2 * p + 1]);
                }
            }
        }
#pragma unroll
        for (int pp = 0; pp < 16; pp++) {
            float2 hv = unpack2(h[pp]);
            float h0 = fmaxf(hv.x, 0.f), h1 = fmaxf(hv.y, 0.f);
            int j0 = half * 32 + 2 * pp;
            uint64_t h02 = pack2(h0, h0), h12 = pack2(h1, h1);
            const ulonglong2* r0 = (const ulonglong2*)(sW2 + j0 * Dm);
            const ulonglong2* r1 = (const ulonglong2*)(sW2 + (j0 + 1) * Dm);
#pragma unroll
            for (int q = 0; q < 8; q++) {
                ulonglong2 w0 = r0[q];
                out[2 * q]     = ffma2(h02, w0.x, out[2 * q]);
                out[2 * q + 1] = ffma2(h02, w0.y, out[2 * q + 1]);
                ulonglong2 w1 = r1[q];
                out[2 * q]     = ffma2(h12, w1.x, out[2 * q]);
                out[2 * q + 1] = ffma2(h12, w1.y, out[2 * q + 1]);
            }
        }
    }
    ulonglong2* xo = (ulonglong2*)(x + (size_t)n * Dm);
#pragma unroll
    for (int q = 0; q < 8; q++) { ulonglong2 v; v.x = out[2 * q]; v.y = out[2 * q + 1]; xo[q] = v; }
}

// ---------------- per-layer: global MLP (sorted-batch segment reduce) -------
static __device__ __forceinline__ int lowerb(const int* __restrict__ a, int n, int v) {
    int lo = 0, hi = n;
    while (lo < hi) { int m = (lo + hi) >> 1; if (a[m] < v) lo = m + 1; else hi = m; }
    return lo;
}
__global__ void k_glob(float* __restrict__ u, const float* __restrict__ x,
                       const int* __restrict__ batch,
                       const float* __restrict__ W1, const float* __restrict__ b1,
                       const float* __restrict__ W2, const float* __restrict__ b2, int N) {
    int b = blockIdx.x, t = threadIdx.x;       // 128 threads
    __shared__ int sLo, sHi;
    if (t == 0) { sLo = lowerb(batch, N, b); sHi = lowerb(batch, N, b + 1); }
    __syncthreads();
    int lo = sLo, hi = sHi;
    float cnt = fmaxf((float)(hi - lo), 1.0f);
    int c = t & 31, g = t >> 5;
    float acc = 0.f;
    for (int r = lo + g; r < hi; r += 4) acc += x[(size_t)r * Dm + c];
    __shared__ float sred[4][Dm];
    sred[g][c] = acc;
    __syncthreads();
    __shared__ float su[2 * Dm];
    __shared__ float sh[Hm];
    if (t < Dm) su[t] = u[b * Dm + t];
    else if (t < 2 * Dm) {
        int cc = t - Dm;
        su[t] = (sred[0][cc] + sred[1][cc] + sred[2][cc] + sred[3][cc]) / cnt;
    }
    __syncthreads();
    if (t < Hm) {
        float h = b1[t];
#pragma unroll 4
        for (int k = 0; k < 2 * Dm; k++) h += su[k] * W1[k * Hm + t];
        sh[t] = fmaxf(h, 0.f);
    }
    __syncthreads();
    if (t < Dm) {
        float o = b2[t];
#pragma unroll 4
        for (int k = 0; k < Hm; k++) o += sh[k] * W2[k * Dm + t];
        u[b * Dm + t] = o;
    }
}

// ---------------- launch ----------------------------------------------------
extern "C" void kernel_launch(void* const* d_in, const int* in_sizes, int n_in,
                              void* d_out, int out_size) {
    const float* node_feats = (const float*)d_in[0];
    const int*   edge_index = (const int*)  d_in[1];
    const float* edge_feats = (const float*)d_in[2];
    const float* glob_feats = (const float*)d_in[3];
    const int*   batch      = (const int*)  d_in[4];
    const float* ngam = (const float*)d_in[5];
    const float* nbet = (const float*)d_in[6];
    const float* egam = (const float*)d_in[7];
    const float* ebet = (const float*)d_in[8];
    const float* ggam = (const float*)d_in[9];
    const float* gbet = (const float*)d_in[10];
    const float* eW1 = (const float*)d_in[11];
    const float* eb1 = (const float*)d_in[12];
    const float* eW2 = (const float*)d_in[13];
    const float* eb2 = (const float*)d_in[14];
    const float* nW1 = (const float*)d_in[15];
    const float* nb1 = (const float*)d_in[16];
    const float* nW2 = (const float*)d_in[17];
    const float* nb2 = (const float*)d_in[18];
    const float* gW1 = (const float*)d_in[19];
    const float* gb1 = (const float*)d_in[20];
    const float* gW2 = (const float*)d_in[21];
    const float* gb2 = (const float*)d_in[22];

    const int N = in_sizes[0] / Dm;
    const int E = in_sizes[2] / Dm;
    const int B = in_sizes[3] / Dm;

    float* x = (float*)d_out;
    float* e = x + (size_t)N * Dm;
    float* u = e + (size_t)E * Dm;
    const int* src = edge_index;
    const int* dst = edge_index + E;

    const int TB = 256;
    int EB = (E * 8 + TB - 1) / TB;
    int XB = (N * 8 + TB - 1) / TB;
    int gE = (E + TB - 1) / TB;
    int gN = (N + TB - 1) / TB;

    // launch 0: fused BN + zero deg
    k_bn_all<<<EB + XB + 1, TB>>>((const float4*)node_feats, (const float4*)edge_feats,
                                  (const float4*)glob_feats,
                                  (float4*)x, (float4*)e, (float4*)u,
                                  ngam, nbet, egam, ebet, ggam, gbet, N, E, B, EB, XB);
    // launch 1: degree count
    k_count_deg<<<gE, TB>>>(dst, E);

    for (int l = 0; l < 3; l++) {
        const float* eW1l = eW1 + (size_t)l * 4 * Dm * Hm;
        const float* nW1l = nW1 + (size_t)l * 3 * Dm * Hm;
        const float* gW1l = gW1 + (size_t)l * 2 * Dm * Hm;
        k_pre_hu<<<gN + 1, TB>>>(x, u, eW1l, eb1 + l * Hm, nW1l, nb1 + l * Hm, N, B);
        k_edge<<<gE, TB>>>(src, dst, batch, e,
                           eW1l + 2 * Dm * Hm,
                           eW2 + (size_t)l * Hm * Dm, eb2 + l * Dm, E);
        k_node<<<gN, TB>>>(x, batch, nW1l,
                           nW2 + (size_t)l * Hm * Dm, nb2 + l * Dm, N);
        k_glob<<<B, 128>>>(u, x, batch, gW1l, gb1 + l * Hm,
                           gW2 + (size_t)l * Hm * Dm, gb2 + l * Dm, N);
    }
}

// round 6
// speedup vs baseline: 2.6470x; 1.2080x over previous
#include <cuda_runtime.h>
#include <cstdint>

#define Dm 32
#define Hm 64
#define NMAX 50000
#define BMAX 16
#define TE 256
#define SEIN 260
#define SBST 68
#define SMEM_EDGE_BYTES ((32 * SEIN + 256 * SBST) * 4)

// ---------------- scratch ----------------------------------------------------
__device__ __align__(16) float g_A  [NMAX * Hm];   // A' = x@W1a + hU[batch]
__device__ __align__(16) float g_Bp [NMAX * Hm];   // B  = x@W1b
__device__ __align__(16) float g_agg[NMAX * Dm];
__device__ __align__(16) float g_hU [BMAX * Hm];
__device__ __align__(16) float g_hUn[BMAX * Hm];
__device__ float g_deg [NMAX];
__device__ float g_rdeg[NMAX];

// ---------------- packed f32x2 helpers ---------------------------------------
static __device__ __forceinline__ uint64_t ffma2(uint64_t a, uint64_t b, uint64_t c) {
    uint64_t d; asm("fma.rn.f32x2 %0, %1, %2, %3;" : "=l"(d) : "l"(a), "l"(b), "l"(c));
    return d;
}
static __device__ __forceinline__ uint64_t pack2(float lo, float hi) {
    uint64_t r; asm("mov.b64 %0, {%1, %2};" : "=l"(r) : "f"(lo), "f"(hi));
    return r;
}
static __device__ __forceinline__ float2 unpack2(uint64_t v) {
    float lo, hi; asm("mov.b64 {%0, %1}, %2;" : "=f"(lo), "=f"(hi) : "l"(v));
    float2 f; f.x = lo; f.y = hi; return f;
}
static __device__ __forceinline__ void red_add_v4(float* p, float a, float b, float c, float d) {
    asm volatile("red.global.add.v4.f32 [%0], {%1, %2, %3, %4};"
                 :: "l"(p), "f"(a), "f"(b), "f"(c), "f"(d) : "memory");
}

// ---------------- BN for x and u (+ zero deg) --------------------------------
__global__ void k_bn_xu(const float4* __restrict__ nf, const float4* __restrict__ gf,
                        float4* __restrict__ x, float4* __restrict__ u,
                        const float* __restrict__ ngam, const float* __restrict__ nbet,
                        const float* __restrict__ ggam, const float* __restrict__ gbet,
                        int N, int B, int XB) {
    const float r = rsqrtf(1.0f + 1e-5f);
    int bid = blockIdx.x, t = threadIdx.x;
    const float4* in; float4* out; const float* gm; const float* bt; int i4, lim;
    if (bid < XB) { i4 = bid * 256 + t; lim = N * 8; in = nf; out = x; gm = ngam; bt = nbet;
                    if (i4 < N) g_deg[i4] = 0.0f; }
    else          { i4 = t;             lim = B * 8; in = gf; out = u; gm = ggam; bt = gbet; }
    if (i4 >= lim) return;
    float4 v = in[i4];
    int c = (i4 * 4) & (Dm - 1);
    v.x = v.x * (gm[c + 0] * r) + bt[c + 0];
    v.y = v.y * (gm[c + 1] * r) + bt[c + 1];
    v.z = v.z * (gm[c + 2] * r) + bt[c + 2];
    v.w = v.w * (gm[c + 3] * r) + bt[c + 3];
    out[i4] = v;
}

__global__ void k_count_deg(const int* __restrict__ dst, int E) {
    int i = blockIdx.x * blockDim.x + threadIdx.x;
    if (i < E) atomicAdd(&g_deg[dst[i]], 1.0f);
}

// ---------------- per-layer: hU / hUn (tiny; ebet fold on layer 0) -----------
__global__ void k_hu(const float* __restrict__ u,
                     const float* __restrict__ eW1, const float* __restrict__ eb1,
                     const float* __restrict__ nW1, const float* __restrict__ nb1,
                     const float* __restrict__ ebet, int B) {
    int j = threadIdx.x;   // 64 threads
    float c = 0.f;
    if (ebet) {            // layer 0: BN shift of e folded through W1c
#pragma unroll 4
        for (int k = 0; k < Dm; k++) c += ebet[k] * eW1[(2 * Dm + k) * Hm + j];
    }
    for (int b = 0; b < B; b++) {
        float hu = eb1[j] + c, hun = nb1[j];
#pragma unroll 4
        for (int k = 0; k < Dm; k++) {
            float uv = u[b * Dm + k];
            hu  += uv * eW1[(3 * Dm + k) * Hm + j];
            hun += uv * nW1[(2 * Dm + k) * Hm + j];
        }
        g_hU [b * Hm + j] = hu;
        g_hUn[b * Hm + j] = hun;
    }
}

// ---------------- per-layer: A'/B precompute + rdeg + zero agg ---------------
__global__ void __launch_bounds__(256) k_pre(const float* __restrict__ x,
                                             const int* __restrict__ batch,
                                             const float* __restrict__ eW1, int N) {
    __shared__ __align__(16) float sW[2 * Dm * Hm];
    int t = threadIdx.x;
    for (int i = t; i < 2 * Dm * Hm; i += 256) sW[i] = eW1[i];
    __syncthreads();
    int n = blockIdx.x * 256 + t;
    if (n >= N) return;

    g_rdeg[n] = 1.0f / fmaxf(g_deg[n], 1.0f);
    float4 z = make_float4(0.f, 0.f, 0.f, 0.f);
    float4* pag = (float4*)(g_agg + (size_t)n * Dm);
#pragma unroll
    for (int i = 0; i < 8; i++) pag[i] = z;

    int bb = batch[n];
    const ulonglong2* phu = (const ulonglong2*)(g_hU + bb * Hm);

    float xr[Dm];
    const float4* px = (const float4*)(x + (size_t)n * Dm);
#pragma unroll
    for (int i = 0; i < 8; i++) {
        float4 v = px[i];
        xr[4 * i] = v.x; xr[4 * i + 1] = v.y; xr[4 * i + 2] = v.z; xr[4 * i + 3] = v.w;
    }
#pragma unroll
    for (int half = 0; half < 2; half++) {
        uint64_t a[16], b[16];
#pragma unroll
        for (int p = 0; p < 8; p++) {
            ulonglong2 hv = __ldg(phu + half * 8 + p);
            a[2 * p] = hv.x; a[2 * p + 1] = hv.y;
            b[2 * p] = 0ull; b[2 * p + 1] = 0ull;
        }
#pragma unroll 4
        for (int k = 0; k < Dm; k++) {
            uint64_t xk = pack2(xr[k], xr[k]);
            const ulonglong2* rA = (const ulonglong2*)(sW + k * Hm + half * 32);
            const ulonglong2* rB = (const ulonglong2*)(sW + (Dm + k) * Hm + half * 32);
#pragma unroll
            for (int p = 0; p < 8; p++) {
                ulonglong2 wa = rA[p];
                a[2 * p]     = ffma2(xk, wa.x, a[2 * p]);
                a[2 * p + 1] = ffma2(xk, wa.y, a[2 * p + 1]);
                ulonglong2 wb = rB[p];
                b[2 * p]     = ffma2(xk, wb.x, b[2 * p]);
                b[2 * p + 1] = ffma2(xk, wb.y, b[2 * p + 1]);
            }
        }
        uint64_t* oA = (uint64_t*)(g_A  + (size_t)n * Hm + half * 32);
        uint64_t* oB = (uint64_t*)(g_Bp + (size_t)n * Hm + half * 32);
#pragma unroll
        for (int p = 0; p < 16; p++) { oA[p] = a[p]; oB[p] = b[p]; }
    }
}

// ---------------- per-layer: edge MLP — register-tiled block GEMMs -----------
__global__ void __launch_bounds__(256, 2) k_edge(
    const int* __restrict__ src, const int* __restrict__ dst,
    const float* __restrict__ ein, float* __restrict__ eout,
    const float* __restrict__ W1c, const float* __restrict__ W2,
    const float* __restrict__ b2, const float* __restrict__ escale, int E)
{
    extern __shared__ float smem[];
    float* sEinT = smem;                  // [32][260], quad-swizzled by row>>2
    float* sU    = smem + 32 * SEIN;      // bias[256][68]  then  HT[64][256]
    __shared__ int sS[TE], sD[TE];
    __shared__ float sSc[Dm];
    int t = threadIdx.x;
    int e0 = blockIdx.x * TE;

    if (t < Dm) sSc[t] = escale ? escale[t] * rsqrtf(1.0f + 1e-5f) : 1.0f;
    int ei = min(e0 + t, E - 1);
    sS[t] = src[ei]; sD[t] = dst[ei];
    __syncthreads();

    // ---- stage bias[e][64] = A'[src] + B[dst] ----
    {
        int l16 = t & 15, g16 = t >> 4;
#pragma unroll 4
        for (int p = 0; p < 16; p++) {
            int eL = p * 16 + g16;
            float4 av = __ldg((const float4*)(g_A  + (size_t)sS[eL] * Hm) + l16);
            float4 bv = __ldg((const float4*)(g_Bp + (size_t)sD[eL] * Hm) + l16);
            *(float4*)(sU + eL * SBST + l16 * 4) =
                make_float4(av.x + bv.x, av.y + bv.y, av.z + bv.z, av.w + bv.w);
        }
    }
    // ---- stage Ein transposed, quad swizzle q ^ (row>>2), BN scale fold ----
    {
        int l8 = t & 7, g8 = t >> 3;
        int k0 = l8 * 4;
        float s0 = sSc[k0], s1 = sSc[k0 + 1], s2 = sSc[k0 + 2], s3 = sSc[k0 + 3];
#pragma unroll 2
        for (int p = 0; p < 8; p++) {
            int eL = p * 32 + g8;
            int eg = min(e0 + eL, E - 1);
            float4 v = __ldg((const float4*)(ein + (size_t)eg * Dm) + l8);
            int col = (((eL >> 2) ^ l8) << 2) + (eL & 3);
            sEinT[(k0 + 0) * SEIN + col] = v.x * s0;
            sEinT[(k0 + 1) * SEIN + col] = v.y * s1;
            sEinT[(k0 + 2) * SEIN + col] = v.z * s2;
            sEinT[(k0 + 3) * SEIN + col] = v.w * s3;
        }
    }
    __syncthreads();

    // ---- GEMM1: H[256x64] = EinT^T @ W1c + bias; tile 8 edges x 8 j ----
    int jb = t & 7, ebk = t >> 3;
    uint64_t acc[8][4];
#pragma unroll
    for (int i = 0; i < 8; i++) {
        const ulonglong2* pb = (const ulonglong2*)(sU + (ebk * 8 + i) * SBST + jb * 8);
        ulonglong2 b0 = pb[0], b1 = pb[1];
        acc[i][0] = b0.x; acc[i][1] = b0.y; acc[i][2] = b1.x; acc[i][3] = b1.y;
    }
    __syncthreads();   // bias region now free for HT

#pragma unroll 4
    for (int k = 0; k < Dm; k++) {
        int sw = k >> 2;
        const float4* pe = (const float4*)(sEinT + k * SEIN);
        float4 ea = pe[(ebk * 2) ^ sw];
        float4 eb = pe[(ebk * 2 + 1) ^ sw];
        ulonglong2 wA = __ldg((const ulonglong2*)(W1c + k * Hm + jb * 8));
        ulonglong2 wB = __ldg((const ulonglong2*)(W1c + k * Hm + jb * 8 + 4));
        float ev[8] = {ea.x, ea.y, ea.z, ea.w, eb.x, eb.y, eb.z, eb.w};
#pragma unroll
        for (int i = 0; i < 8; i++) {
            uint64_t ed = pack2(ev[i], ev[i]);
            acc[i][0] = ffma2(ed, wA.x, acc[i][0]);
            acc[i][1] = ffma2(ed, wA.y, acc[i][1]);
            acc[i][2] = ffma2(ed, wB.x, acc[i][2]);
            acc[i][3] = ffma2(ed, wB.y, acc[i][3]);
        }
    }

    // ---- relu + store H^T [64][256], quad swizzle q ^ (j>>3) ----
    float* sHT = sU;
#pragma unroll
    for (int jj = 0; jj < 8; jj++) {
        int j = jb * 8 + jj;
        float f[8];
#pragma unroll
        for (int i = 0; i < 8; i++) {
            float2 v = unpack2(acc[i][jj >> 1]);
            f[i] = fmaxf((jj & 1) ? v.y : v.x, 0.f);
        }
        *(float4*)(sHT + j * 256 + (((ebk * 2)     ^ jb) << 2)) = make_float4(f[0], f[1], f[2], f[3]);
        *(float4*)(sHT + j * 256 + (((ebk * 2 + 1) ^ jb) << 2)) = make_float4(f[4], f[5], f[6], f[7]);
    }
    __syncthreads();

    // ---- GEMM2: OUT[256x32] = relu(H) @ W2 + b2; tile 8 edges x 4 j ----
    uint64_t out[8][2];
    {
        ulonglong2 bb = __ldg((const ulonglong2*)(b2 + jb * 4));
#pragma unroll
        for (int i = 0; i < 8; i++) { out[i][0] = bb.x; out[i][1] = bb.y; }
    }
#pragma unroll 4
    for (int k = 0; k < Hm; k++) {
        int sw = (k >> 3) & 7;
        const float4* ph = (const float4*)(sHT + k * 256);
        float4 h0 = ph[(ebk * 2) ^ sw];
        float4 h1 = ph[(ebk * 2 + 1) ^ sw];
        ulonglong2 w = __ldg((const ulonglong2*)(W2 + k * Dm + jb * 4));
        float hv[8] = {h0.x, h0.y, h0.z, h0.w, h1.x, h1.y, h1.z, h1.w};
#pragma unroll
        for (int i = 0; i < 8; i++) {
            uint64_t hd = pack2(hv[i], hv[i]);
            out[i][0] = ffma2(hd, w.x, out[i][0]);
            out[i][1] = ffma2(hd, w.y, out[i][1]);
        }
    }
    // ---- epilogue: write e + fused RED into agg ----
#pragma unroll
    for (int i = 0; i < 8; i++) {
        int eL = ebk * 8 + i, eg = e0 + eL;
        if (eg < E) {
            float2 a = unpack2(out[i][0]); float2 b = unpack2(out[i][1]);
            *(float4*)(eout + (size_t)eg * Dm + jb * 4) = make_float4(a.x, a.y, b.x, b.y);
            red_add_v4(g_agg + (size_t)sD[eL] * Dm + jb * 4, a.x, a.y, b.x, b.y);
        }
    }
}

// ---------------- per-layer: node MLP ----------------------------------------
__global__ void __launch_bounds__(256, 2) k_node(
    float* __restrict__ x, const int* __restrict__ batch,
    const float* __restrict__ W1, const float* __restrict__ W2, const float* __restrict__ b2,
    int N)
{
    __shared__ __align__(16) float sW1[2 * Dm * Hm];
    __shared__ __align__(16) float sW2[Hm * Dm];
    __shared__ __align__(16) float sHU[BMAX * Hm];
    int t = threadIdx.x;
    for (int i = t; i < 2 * Dm * Hm; i += 256) sW1[i] = W1[i];
    for (int i = t; i < Hm * Dm; i += 256) sW2[i] = W2[i];
    for (int i = t; i < BMAX * Hm; i += 256) sHU[i] = g_hUn[i];
    __syncthreads();
    int n = blockIdx.x * 256 + t;
    if (n >= N) return;

    int b = batch[n];
    float rd = g_rdeg[n];
    const float* xptr = x + (size_t)n * Dm;
    const float* aptr = g_agg + (size_t)n * Dm;

    uint64_t out[16];
    {
        const float4* pb = (const float4*)b2;
#pragma unroll
        for (int q = 0; q < 8; q++) {
            float4 v = __ldg(pb + q);
            out[2 * q] = pack2(v.x, v.y); out[2 * q + 1] = pack2(v.z, v.w);
        }
    }
#pragma unroll
    for (int half = 0; half < 2; half++) {
        uint64_t h[16];
        const ulonglong2* pu = (const ulonglong2*)(sHU + b * Hm + half * 32);
#pragma unroll
        for (int p = 0; p < 8; p++) { ulonglong2 v = pu[p]; h[2 * p] = v.x; h[2 * p + 1] = v.y; }
#pragma unroll
        for (int kc = 0; kc < 8; kc++) {
            float4 ev0, ev1;
            if (kc < 4) { ev0 = __ldg((const float4*)xptr + kc * 2);
                          ev1 = __ldg((const float4*)xptr + kc * 2 + 1); }
            else {
                float4 a0 = __ldg((const float4*)aptr + (kc - 4) * 2);
                float4 a1 = __ldg((const float4*)aptr + (kc - 4) * 2 + 1);
                ev0.x = a0.x * rd; ev0.y = a0.y * rd; ev0.z = a0.z * rd; ev0.w = a0.w * rd;
                ev1.x = a1.x * rd; ev1.y = a1.y * rd; ev1.z = a1.z * rd; ev1.w = a1.w * rd;
            }
            float ech[8] = {ev0.x, ev0.y, ev0.z, ev0.w, ev1.x, ev1.y, ev1.z, ev1.w};
#pragma unroll
            for (int k8 = 0; k8 < 8; k8++) {
                int k = kc * 8 + k8;
                uint64_t ek = pack2(ech[k8], ech[k8]);
                const ulonglong2* wr = (const ulonglong2*)(sW1 + k * Hm + half * 32);
#pragma unroll
                for (int p = 0; p < 8; p++) {
                    ulonglong2 w = wr[p];
                    h[2 * p]     = ffma2(ek, w.x, h[2 * p]);
                    h[2 * p + 1] = ffma2(ek, w.y, h[2 * p + 1]);
                }
            }
        }
#pragma unroll
        for (int pp = 0; pp < 16; pp++) {
            float2 hv = unpack2(h[pp]);
            float h0 = fmaxf(hv.x, 0.f), h1 = fmaxf(hv.y, 0.f);
            int j0 = half * 32 + 2 * pp;
            uint64_t h02 = pack2(h0, h0), h12 = pack2(h1, h1);
            const ulonglong2* r0 = (const ulonglong2*)(sW2 + j0 * Dm);
            const ulonglong2* r1 = (const ulonglong2*)(sW2 + (j0 + 1) * Dm);
#pragma unroll
            for (int q = 0; q < 8; q++) {
                ulonglong2 w0 = r0[q];
                out[2 * q]     = ffma2(h02, w0.x, out[2 * q]);
                out[2 * q + 1] = ffma2(h02, w0.y, out[2 * q + 1]);
                ulonglong2 w1 = r1[q];
                out[2 * q]     = ffma2(h12, w1.x, out[2 * q]);
                out[2 * q + 1] = ffma2(h12, w1.y, out[2 * q + 1]);
            }
        }
    }
    ulonglong2* xo = (ulonglong2*)(x + (size_t)n * Dm);
#pragma unroll
    for (int q = 0; q < 8; q++) { ulonglong2 v; v.x = out[2 * q]; v.y = out[2 * q + 1]; xo[q] = v; }
}

// ---------------- per-layer: global MLP (sorted-batch segment reduce) --------
static __device__ __forceinline__ int lowerb(const int* __restrict__ a, int n, int v) {
    int lo = 0, hi = n;
    while (lo < hi) { int m = (lo + hi) >> 1; if (a[m] < v) lo = m + 1; else hi = m; }
    return lo;
}
__global__ void k_glob(float* __restrict__ u, const float* __restrict__ x,
                       const int* __restrict__ batch,
                       const float* __restrict__ W1, const float* __restrict__ b1,
                       const float* __restrict__ W2, const float* __restrict__ b2, int N) {
    int b = blockIdx.x, t = threadIdx.x;       // 128 threads
    __shared__ int sLo, sHi;
    if (t == 0) { sLo = lowerb(batch, N, b); sHi = lowerb(batch, N, b + 1); }
    __syncthreads();
    int lo = sLo, hi = sHi;
    float cnt = fmaxf((float)(hi - lo), 1.0f);
    int c = t & 31, g = t >> 5;
    float acc = 0.f;
    for (int r = lo + g; r < hi; r += 4) acc += x[(size_t)r * Dm + c];
    __shared__ float sred[4][Dm];
    sred[g][c] = acc;
    __syncthreads();
    __shared__ float su[2 * Dm];
    __shared__ float sh[Hm];
    if (t < Dm) su[t] = u[b * Dm + t];
    else if (t < 2 * Dm) {
        int cc = t - Dm;
        su[t] = (sred[0][cc] + sred[1][cc] + sred[2][cc] + sred[3][cc]) / cnt;
    }
    __syncthreads();
    if (t < Hm) {
        float h = b1[t];
#pragma unroll 4
        for (int k = 0; k < 2 * Dm; k++) h += su[k] * W1[k * Hm + t];
        sh[t] = fmaxf(h, 0.f);
    }
    __syncthreads();
    if (t < Dm) {
        float o = b2[t];
#pragma unroll 4
        for (int k = 0; k < Hm; k++) o += sh[k] * W2[k * Dm + t];
        u[b * Dm + t] = o;
    }
}

// ---------------- launch -----------------------------------------------------
extern "C" void kernel_launch(void* const* d_in, const int* in_sizes, int n_in,
                              void* d_out, int out_size) {
    const float* node_feats = (const float*)d_in[0];
    const int*   edge_index = (const int*)  d_in[1];
    const float* edge_feats = (const float*)d_in[2];
    const float* glob_feats = (const float*)d_in[3];
    const int*   batch      = (const int*)  d_in[4];
    const float* ngam = (const float*)d_in[5];
    const float* nbet = (const float*)d_in[6];
    const float* egam = (const float*)d_in[7];
    const float* ebet = (const float*)d_in[8];
    const float* ggam = (const float*)d_in[9];
    const float* gbet = (const float*)d_in[10];
    const float* eW1 = (const float*)d_in[11];
    const float* eb1 = (const float*)d_in[12];
    const float* eW2 = (const float*)d_in[13];
    const float* eb2 = (const float*)d_in[14];
    const float* nW1 = (const float*)d_in[15];
    const float* nb1 = (const float*)d_in[16];
    const float* nW2 = (const float*)d_in[17];
    const float* nb2 = (const float*)d_in[18];
    const float* gW1 = (const float*)d_in[19];
    const float* gb1 = (const float*)d_in[20];
    const float* gW2 = (const float*)d_in[21];
    const float* gb2 = (const float*)d_in[22];

    const int N = in_sizes[0] / Dm;
    const int E = in_sizes[2] / Dm;
    const int B = in_sizes[3] / Dm;

    float* x = (float*)d_out;
    float* e = x + (size_t)N * Dm;
    float* u = e + (size_t)E * Dm;
    const int* src = edge_index;
    const int* dst = edge_index + E;

    const int TB = 256;
    int XB = (N * 8 + TB - 1) / TB;
    int gE = (E + TB - 1) / TB;
    int gN = (N + TB - 1) / TB;
    int gTE = (E + TE - 1) / TE;

    cudaFuncSetAttribute(k_edge, cudaFuncAttributeMaxDynamicSharedMemorySize, SMEM_EDGE_BYTES);

    k_bn_xu<<<XB + 1, TB>>>((const float4*)node_feats, (const float4*)glob_feats,
                            (float4*)x, (float4*)u, ngam, nbet, ggam, gbet, N, B, XB);
    k_count_deg<<<gE, TB>>>(dst, E);

    for (int l = 0; l < 3; l++) {
        const float* eW1l = eW1 + (size_t)l * 4 * Dm * Hm;   // (128,64)
        const float* nW1l = nW1 + (size_t)l * 3 * Dm * Hm;   // (96,64)
        const float* gW1l = gW1 + (size_t)l * 2 * Dm * Hm;   // (64,64)
        k_hu <<<1, Hm>>>(u, eW1l, eb1 + l * Hm, nW1l, nb1 + l * Hm,
                         (l == 0) ? ebet : (const float*)nullptr, B);
        k_pre<<<gN, TB>>>(x, batch, eW1l, N);
        k_edge<<<gTE, TB, SMEM_EDGE_BYTES>>>(src, dst,
                           (l == 0) ? edge_feats : e, e,
                           eW1l + 2 * Dm * Hm,            // rows 64..95 (e part)
                           eW2 + (size_t)l * Hm * Dm, eb2 + l * Dm,
                           (l == 0) ? egam : (const float*)nullptr, E);
        k_node<<<gN, TB>>>(x, batch, nW1l,
                           nW2 + (size_t)l * Hm * Dm, nb2 + l * Dm, N);
        k_glob<<<B, 128>>>(u, x, batch, gW1l, gb1 + l * Hm,
                           gW2 + (size_t)l * Hm * Dm, gb2 + l * Dm, N);
    }
}

// round 7
// speedup vs baseline: 2.9515x; 1.1150x over previous
#include <cuda_runtime.h>
#include <cstdint>

#define Dm 32
#define Hm 64
#define NMAX 50000
#define BMAX 16
#define TE 256
#define SEIN 260
#define SBST 68
#define SXT 264
#define SMEM_EDGE_BYTES ((32 * SEIN + 256 * SBST) * 4)
#define SMEM_NODE_BYTES (64 * SXT * 4)

// ---------------- scratch ----------------------------------------------------
__device__ __align__(16) float g_A  [NMAX * Hm];   // A' = x@W1a + hU[batch]
__device__ __align__(16) float g_Bp [NMAX * Hm];   // B  = x@W1b
__device__ __align__(16) float g_agg[NMAX * Dm];
__device__ __align__(16) float g_hU [BMAX * Hm];
__device__ __align__(16) float g_hUn[BMAX * Hm];
__device__ float g_deg [NMAX];
__device__ float g_rdeg[NMAX];

// ---------------- packed f32x2 helpers ---------------------------------------
static __device__ __forceinline__ uint64_t ffma2(uint64_t a, uint64_t b, uint64_t c) {
    uint64_t d; asm("fma.rn.f32x2 %0, %1, %2, %3;" : "=l"(d) : "l"(a), "l"(b), "l"(c));
    return d;
}
static __device__ __forceinline__ uint64_t pack2(float lo, float hi) {
    uint64_t r; asm("mov.b64 %0, {%1, %2};" : "=l"(r) : "f"(lo), "f"(hi));
    return r;
}
static __device__ __forceinline__ float2 unpack2(uint64_t v) {
    float lo, hi; asm("mov.b64 {%0, %1}, %2;" : "=f"(lo), "=f"(hi) : "l"(v));
    float2 f; f.x = lo; f.y = hi; return f;
}
static __device__ __forceinline__ void red_add_v4(float* p, float a, float b, float c, float d) {
    asm volatile("red.global.add.v4.f32 [%0], {%1, %2, %3, %4};"
                 :: "l"(p), "f"(a), "f"(b), "f"(c), "f"(d) : "memory");
}

// ---------------- launch 0: BN for x and u (+ zero deg) ----------------------
__global__ void k_bn_xu(const float4* __restrict__ nf, const float4* __restrict__ gf,
                        float4* __restrict__ x, float4* __restrict__ u,
                        const float* __restrict__ ngam, const float* __restrict__ nbet,
                        const float* __restrict__ ggam, const float* __restrict__ gbet,
                        int N, int B, int XB) {
    const float r = rsqrtf(1.0f + 1e-5f);
    int bid = blockIdx.x, t = threadIdx.x;
    const float4* in; float4* out; const float* gm; const float* bt; int i4, lim;
    if (bid < XB) { i4 = bid * 256 + t; lim = N * 8; in = nf; out = x; gm = ngam; bt = nbet;
                    if (i4 < N) g_deg[i4] = 0.0f; }
    else          { i4 = t;             lim = B * 8; in = gf; out = u; gm = ggam; bt = gbet; }
    if (i4 >= lim) return;
    float4 v = in[i4];
    int c = (i4 * 4) & (Dm - 1);
    v.x = v.x * (gm[c + 0] * r) + bt[c + 0];
    v.y = v.y * (gm[c + 1] * r) + bt[c + 1];
    v.z = v.z * (gm[c + 2] * r) + bt[c + 2];
    v.w = v.w * (gm[c + 3] * r) + bt[c + 3];
    out[i4] = v;
}

// ---------------- hU/hUn body -------------------------------------------------
static __device__ __forceinline__ void hu_body(
    const float* __restrict__ u,
    const float* __restrict__ eW1, const float* __restrict__ eb1,
    const float* __restrict__ nW1, const float* __restrict__ nb1,
    const float* __restrict__ ebet, int B, int j)
{
    float c = 0.f;
    if (ebet) {            // layer 0: BN shift of e folded through W1c
#pragma unroll 4
        for (int k = 0; k < Dm; k++) c += ebet[k] * eW1[(2 * Dm + k) * Hm + j];
    }
    for (int b = 0; b < B; b++) {
        float hu = eb1[j] + c, hun = nb1[j];
#pragma unroll 4
        for (int k = 0; k < Dm; k++) {
            float uv = u[b * Dm + k];
            hu  += uv * eW1[(3 * Dm + k) * Hm + j];
            hun += uv * nW1[(2 * Dm + k) * Hm + j];
        }
        g_hU [b * Hm + j] = hu;
        g_hUn[b * Hm + j] = hun;
    }
}

// ---------------- launch 1: deg count + layer-0 hU ----------------------------
__global__ void k_deg_hu(const int* __restrict__ dst, const float* __restrict__ u,
                         const float* __restrict__ eW1, const float* __restrict__ eb1,
                         const float* __restrict__ nW1, const float* __restrict__ nb1,
                         const float* __restrict__ ebet, int E, int B) {
    if (blockIdx.x == gridDim.x - 1) {
        if (threadIdx.x < Hm) hu_body(u, eW1, eb1, nW1, nb1, ebet, B, threadIdx.x);
        return;
    }
    int i = blockIdx.x * blockDim.x + threadIdx.x;
    if (i < E) atomicAdd(&g_deg[dst[i]], 1.0f);
}

// layers 1,2: standalone hU
__global__ void k_hu(const float* __restrict__ u,
                     const float* __restrict__ eW1, const float* __restrict__ eb1,
                     const float* __restrict__ nW1, const float* __restrict__ nb1, int B) {
    if (threadIdx.x < Hm) hu_body(u, eW1, eb1, nW1, nb1, nullptr, B, threadIdx.x);
}

// ---------------- per-layer: A'/B precompute (tiled GEMM) + rdeg + zero agg ---
__global__ void __launch_bounds__(256, 2) k_pre(const float* __restrict__ x,
                                                const int* __restrict__ batch,
                                                const float* __restrict__ eW1, int N) {
    __shared__ __align__(16) float sX[32 * SXT];
    __shared__ int sBt[256];
    int t = threadIdx.x;
    int n0 = blockIdx.x * 256;
    int ng = min(n0 + t, N - 1);
    sBt[t] = batch[ng];
    if (n0 + t < N) g_rdeg[n0 + t] = 1.0f / fmaxf(g_deg[n0 + t], 1.0f);
    {   // zero this block's agg region
        float4 z = make_float4(0.f, 0.f, 0.f, 0.f);
        float4* pz = (float4*)(g_agg + (size_t)n0 * Dm);
        int lim4 = min(256, N - n0) * 8;
        for (int i = t; i < lim4; i += 256) pz[i] = z;
    }
    {   // stage x^T, quad swizzle
        int l8 = t & 7, g8 = t >> 3, k0 = l8 * 4;
#pragma unroll 2
        for (int p = 0; p < 8; p++) {
            int nL = p * 32 + g8;
            int ngl = min(n0 + nL, N - 1);
            float4 v = __ldg((const float4*)(x + (size_t)ngl * Dm) + l8);
            int col = (((nL >> 2) ^ l8) << 2) + (nL & 3);
            sX[(k0 + 0) * SXT + col] = v.x;
            sX[(k0 + 1) * SXT + col] = v.y;
            sX[(k0 + 2) * SXT + col] = v.z;
            sX[(k0 + 3) * SXT + col] = v.w;
        }
    }
    __syncthreads();

    int jb = t & 7, nbk = t >> 3;
    uint64_t acc[8][4];
#pragma unroll
    for (int g = 0; g < 2; g++) {               // g=0: A' (rows 0..31, hU bias); g=1: B (rows 32..63)
        const float* W = eW1 + g * Dm * Hm;
        float* O = g ? g_Bp : g_A;
#pragma unroll
        for (int i = 0; i < 8; i++) {
            if (g == 0) {
                int bb = sBt[nbk * 8 + i];
                const ulonglong2* pb = (const ulonglong2*)(g_hU + bb * Hm + jb * 8);
                ulonglong2 b0 = __ldg(pb), b1 = __ldg(pb + 1);
                acc[i][0] = b0.x; acc[i][1] = b0.y; acc[i][2] = b1.x; acc[i][3] = b1.y;
            } else {
                acc[i][0] = acc[i][1] = acc[i][2] = acc[i][3] = 0ull;
            }
        }
#pragma unroll 4
        for (int k = 0; k < Dm; k++) {
            int sw = k >> 2;
            const float4* pe = (const float4*)(sX + k * SXT);
            float4 ea = pe[(nbk * 2) ^ sw];
            float4 eb = pe[(nbk * 2 + 1) ^ sw];
            ulonglong2 wA = __ldg((const ulonglong2*)(W + k * Hm + jb * 8));
            ulonglong2 wB = __ldg((const ulonglong2*)(W + k * Hm + jb * 8 + 4));
            float ev[8] = {ea.x, ea.y, ea.z, ea.w, eb.x, eb.y, eb.z, eb.w};
#pragma unroll
            for (int i = 0; i < 8; i++) {
                uint64_t ed = pack2(ev[i], ev[i]);
                acc[i][0] = ffma2(ed, wA.x, acc[i][0]);
                acc[i][1] = ffma2(ed, wA.y, acc[i][1]);
                acc[i][2] = ffma2(ed, wB.x, acc[i][2]);
                acc[i][3] = ffma2(ed, wB.y, acc[i][3]);
            }
        }
#pragma unroll
        for (int i = 0; i < 8; i++) {
            int n = n0 + nbk * 8 + i;
            if (n < N) {
                float2 a0 = unpack2(acc[i][0]), a1 = unpack2(acc[i][1]);
                float2 a2 = unpack2(acc[i][2]), a3 = unpack2(acc[i][3]);
                *(float4*)(O + (size_t)n * Hm + jb * 8)     = make_float4(a0.x, a0.y, a1.x, a1.y);
                *(float4*)(O + (size_t)n * Hm + jb * 8 + 4) = make_float4(a2.x, a2.y, a3.x, a3.y);
            }
        }
    }
}

// ---------------- per-layer: edge MLP — register-tiled block GEMMs -----------
__global__ void __launch_bounds__(256, 2) k_edge(
    const int* __restrict__ src, const int* __restrict__ dst,
    const float* __restrict__ ein, float* __restrict__ eout,
    const float* __restrict__ W1c, const float* __restrict__ W2,
    const float* __restrict__ b2, const float* __restrict__ escale, int E)
{
    extern __shared__ float smem[];
    float* sEinT = smem;                  // [32][260], quad-swizzled by row>>2
    float* sU    = smem + 32 * SEIN;      // bias[256][68]  then  HT[64][256]
    __shared__ int sS[TE], sD[TE];
    __shared__ float sSc[Dm];
    int t = threadIdx.x;
    int e0 = blockIdx.x * TE;

    if (t < Dm) sSc[t] = escale ? escale[t] * rsqrtf(1.0f + 1e-5f) : 1.0f;
    int ei = min(e0 + t, E - 1);
    sS[t] = src[ei]; sD[t] = dst[ei];
    __syncthreads();

    // ---- stage bias[e][64] = A'[src] + B[dst] ----
    {
        int l16 = t & 15, g16 = t >> 4;
#pragma unroll 4
        for (int p = 0; p < 16; p++) {
            int eL = p * 16 + g16;
            float4 av = __ldg((const float4*)(g_A  + (size_t)sS[eL] * Hm) + l16);
            float4 bv = __ldg((const float4*)(g_Bp + (size_t)sD[eL] * Hm) + l16);
            *(float4*)(sU + eL * SBST + l16 * 4) =
                make_float4(av.x + bv.x, av.y + bv.y, av.z + bv.z, av.w + bv.w);
        }
    }
    // ---- stage Ein transposed, quad swizzle, BN scale fold ----
    {
        int l8 = t & 7, g8 = t >> 3;
        int k0 = l8 * 4;
        float s0 = sSc[k0], s1 = sSc[k0 + 1], s2 = sSc[k0 + 2], s3 = sSc[k0 + 3];
#pragma unroll 2
        for (int p = 0; p < 8; p++) {
            int eL = p * 32 + g8;
            int eg = min(e0 + eL, E - 1);
            float4 v = __ldg((const float4*)(ein + (size_t)eg * Dm) + l8);
            int col = (((eL >> 2) ^ l8) << 2) + (eL & 3);
            sEinT[(k0 + 0) * SEIN + col] = v.x * s0;
            sEinT[(k0 + 1) * SEIN + col] = v.y * s1;
            sEinT[(k0 + 2) * SEIN + col] = v.z * s2;
            sEinT[(k0 + 3) * SEIN + col] = v.w * s3;
        }
    }
    __syncthreads();

    // ---- GEMM1: H[256x64] ----
    int jb = t & 7, ebk = t >> 3;
    uint64_t acc[8][4];
#pragma unroll
    for (int i = 0; i < 8; i++) {
        const ulonglong2* pb = (const ulonglong2*)(sU + (ebk * 8 + i) * SBST + jb * 8);
        ulonglong2 b0 = pb[0], b1 = pb[1];
        acc[i][0] = b0.x; acc[i][1] = b0.y; acc[i][2] = b1.x; acc[i][3] = b1.y;
    }
    __syncthreads();   // bias region now free for HT

#pragma unroll 4
    for (int k = 0; k < Dm; k++) {
        int sw = k >> 2;
        const float4* pe = (const float4*)(sEinT + k * SEIN);
        float4 ea = pe[(ebk * 2) ^ sw];
        float4 eb = pe[(ebk * 2 + 1) ^ sw];
        ulonglong2 wA = __ldg((const ulonglong2*)(W1c + k * Hm + jb * 8));
        ulonglong2 wB = __ldg((const ulonglong2*)(W1c + k * Hm + jb * 8 + 4));
        float ev[8] = {ea.x, ea.y, ea.z, ea.w, eb.x, eb.y, eb.z, eb.w};
#pragma unroll
        for (int i = 0; i < 8; i++) {
            uint64_t ed = pack2(ev[i], ev[i]);
            acc[i][0] = ffma2(ed, wA.x, acc[i][0]);
            acc[i][1] = ffma2(ed, wA.y, acc[i][1]);
            acc[i][2] = ffma2(ed, wB.x, acc[i][2]);
            acc[i][3] = ffma2(ed, wB.y, acc[i][3]);
        }
    }

    // ---- relu + store H^T [64][256], quad swizzle q ^ jb ----
    float* sHT = sU;
#pragma unroll
    for (int jj = 0; jj < 8; jj++) {
        int j = jb * 8 + jj;
        float f[8];
#pragma unroll
        for (int i = 0; i < 8; i++) {
            float2 v = unpack2(acc[i][jj >> 1]);
            f[i] = fmaxf((jj & 1) ? v.y : v.x, 0.f);
        }
        *(float4*)(sHT + j * 256 + (((ebk * 2)     ^ jb) << 2)) = make_float4(f[0], f[1], f[2], f[3]);
        *(float4*)(sHT + j * 256 + (((ebk * 2 + 1) ^ jb) << 2)) = make_float4(f[4], f[5], f[6], f[7]);
    }
    __syncthreads();

    // ---- GEMM2: OUT[256x32] ----
    uint64_t out[8][2];
    {
        ulonglong2 bb = __ldg((const ulonglong2*)(b2 + jb * 4));
#pragma unroll
        for (int i = 0; i < 8; i++) { out[i][0] = bb.x; out[i][1] = bb.y; }
    }
#pragma unroll 4
    for (int k = 0; k < Hm; k++) {
        int sw = (k >> 3) & 7;
        const float4* ph = (const float4*)(sHT + k * 256);
        float4 h0 = ph[(ebk * 2) ^ sw];
        float4 h1 = ph[(ebk * 2 + 1) ^ sw];
        ulonglong2 w = __ldg((const ulonglong2*)(W2 + k * Dm + jb * 4));
        float hv[8] = {h0.x, h0.y, h0.z, h0.w, h1.x, h1.y, h1.z, h1.w};
#pragma unroll
        for (int i = 0; i < 8; i++) {
            uint64_t hd = pack2(hv[i], hv[i]);
            out[i][0] = ffma2(hd, w.x, out[i][0]);
            out[i][1] = ffma2(hd, w.y, out[i][1]);
        }
    }
    // ---- epilogue: write e + fused RED into agg ----
#pragma unroll
    for (int i = 0; i < 8; i++) {
        int eL = ebk * 8 + i, eg = e0 + eL;
        if (eg < E) {
            float2 a = unpack2(out[i][0]); float2 b = unpack2(out[i][1]);
            *(float4*)(eout + (size_t)eg * Dm + jb * 4) = make_float4(a.x, a.y, b.x, b.y);
            red_add_v4(g_agg + (size_t)sD[eL] * Dm + jb * 4, a.x, a.y, b.x, b.y);
        }
    }
}

// ---------------- per-layer: node MLP — register-tiled block GEMMs -----------
__global__ void __launch_bounds__(256, 2) k_node(
    float* __restrict__ x, const int* __restrict__ batch,
    const float* __restrict__ W1, const float* __restrict__ W2, const float* __restrict__ b2,
    int N)
{
    extern __shared__ float smem[];
    float* sIn = smem;     // [64][264]: rows 0..31 = x^T, rows 32..63 = (agg*rd)^T
    float* sHT = smem;     // overlay after GEMM1: [64][256]
    __shared__ int sBt[256];
    int t = threadIdx.x;
    int n0 = blockIdx.x * 256;
    sBt[t] = batch[min(n0 + t, N - 1)];
    {
        int l8 = t & 7, g8 = t >> 3, k0 = l8 * 4;
#pragma unroll 2
        for (int p = 0; p < 8; p++) {
            int nL = p * 32 + g8;
            int ngl = min(n0 + nL, N - 1);
            float4 vx = __ldg((const float4*)(x + (size_t)ngl * Dm) + l8);
            float rd = g_rdeg[ngl];
            float4 va = __ldg((const float4*)(g_agg + (size_t)ngl * Dm) + l8);
            int col = (((nL >> 2) ^ l8) << 2) + (nL & 3);
            sIn[(k0 + 0) * SXT + col] = vx.x;
            sIn[(k0 + 1) * SXT + col] = vx.y;
            sIn[(k0 + 2) * SXT + col] = vx.z;
            sIn[(k0 + 3) * SXT + col] = vx.w;
            sIn[(Dm + k0 + 0) * SXT + col] = va.x * rd;
            sIn[(Dm + k0 + 1) * SXT + col] = va.y * rd;
            sIn[(Dm + k0 + 2) * SXT + col] = va.z * rd;
            sIn[(Dm + k0 + 3) * SXT + col] = va.w * rd;
        }
    }
    __syncthreads();

    // ---- GEMM1: H[256x64] = In^T @ W1(rows 0..63) + hUn[batch] ----
    int jb = t & 7, nbk = t >> 3;
    uint64_t acc[8][4];
#pragma unroll
    for (int i = 0; i < 8; i++) {
        int bb = sBt[nbk * 8 + i];
        const ulonglong2* pb = (const ulonglong2*)(g_hUn + bb * Hm + jb * 8);
        ulonglong2 b0 = __ldg(pb), b1 = __ldg(pb + 1);
        acc[i][0] = b0.x; acc[i][1] = b0.y; acc[i][2] = b1.x; acc[i][3] = b1.y;
    }
#pragma unroll 4
    for (int k = 0; k < 2 * Dm; k++) {
        int sw = (k >> 2) & 7;
        const float4* pe = (const float4*)(sIn + k * SXT);
        float4 ea = pe[(nbk * 2) ^ sw];
        float4 eb = pe[(nbk * 2 + 1) ^ sw];
        ulonglong2 wA = __ldg((const ulonglong2*)(W1 + k * Hm + jb * 8));
        ulonglong2 wB = __ldg((const ulonglong2*)(W1 + k * Hm + jb * 8 + 4));
        float ev[8] = {ea.x, ea.y, ea.z, ea.w, eb.x, eb.y, eb.z, eb.w};
#pragma unroll
        for (int i = 0; i < 8; i++) {
            uint64_t ed = pack2(ev[i], ev[i]);
            acc[i][0] = ffma2(ed, wA.x, acc[i][0]);
            acc[i][1] = ffma2(ed, wA.y, acc[i][1]);
            acc[i][2] = ffma2(ed, wB.x, acc[i][2]);
            acc[i][3] = ffma2(ed, wB.y, acc[i][3]);
        }
    }
    __syncthreads();   // all reads of sIn complete before HT overlay

#pragma unroll
    for (int jj = 0; jj < 8; jj++) {
        int j = jb * 8 + jj;
        float f[8];
#pragma unroll
        for (int i = 0; i < 8; i++) {
            float2 v = unpack2(acc[i][jj >> 1]);
            f[i] = fmaxf((jj & 1) ? v.y : v.x, 0.f);
        }
        *(float4*)(sHT + j * 256 + (((nbk * 2)     ^ jb) << 2)) = make_float4(f[0], f[1], f[2], f[3]);
        *(float4*)(sHT + j * 256 + (((nbk * 2 + 1) ^ jb) << 2)) = make_float4(f[4], f[5], f[6], f[7]);
    }
    __syncthreads();

    // ---- GEMM2: OUT[256x32] = relu(H) @ W2 + b2 ----
    uint64_t out[8][2];
    {
        ulonglong2 bb = __ldg((const ulonglong2*)(b2 + jb * 4));
#pragma unroll
        for (int i = 0; i < 8; i++) { out[i][0] = bb.x; out[i][1] = bb.y; }
    }
#pragma unroll 4
    for (int k = 0; k < Hm; k++) {
        int sw = (k >> 3) & 7;
        const float4* ph = (const float4*)(sHT + k * 256);
        float4 h0 = ph[(nbk * 2) ^ sw];
        float4 h1 = ph[(nbk * 2 + 1) ^ sw];
        ulonglong2 w = __ldg((const ulonglong2*)(W2 + k * Dm + jb * 4));
        float hv[8] = {h0.x, h0.y, h0.z, h0.w, h1.x, h1.y, h1.z, h1.w};
#pragma unroll
        for (int i = 0; i < 8; i++) {
            uint64_t hd = pack2(hv[i], hv[i]);
            out[i][0] = ffma2(hd, w.x, out[i][0]);
            out[i][1] = ffma2(hd, w.y, out[i][1]);
        }
    }
#pragma unroll
    for (int i = 0; i < 8; i++) {
        int n = n0 + nbk * 8 + i;
        if (n < N) {
            float2 a = unpack2(out[i][0]); float2 b = unpack2(out[i][1]);
            *(float4*)(x + (size_t)n * Dm + jb * 4) = make_float4(a.x, a.y, b.x, b.y);
        }
    }
}

// ---------------- per-layer: global MLP (sorted-batch segment reduce) --------
static __device__ __forceinline__ int lowerb(const int* __restrict__ a, int n, int v) {
    int lo = 0, hi = n;
    while (lo < hi) { int m = (lo + hi) >> 1; if (a[m] < v) lo = m + 1; else hi = m; }
    return lo;
}
__global__ void k_glob(float* __restrict__ u, const float* __restrict__ x,
                       const int* __restrict__ batch,
                       const float* __restrict__ W1, const float* __restrict__ b1,
                       const float* __restrict__ W2, const float* __restrict__ b2, int N) {
    int b = blockIdx.x, t = threadIdx.x;       // 128 threads
    __shared__ int sLo, sHi;
    if (t == 0) { sLo = lowerb(batch, N, b); sHi = lowerb(batch, N, b + 1); }
    __syncthreads();
    int lo = sLo, hi = sHi;
    float cnt = fmaxf((float)(hi - lo), 1.0f);
    int c = t & 31, g = t >> 5;
    float acc = 0.f;
    for (int r = lo + g; r < hi; r += 4) acc += x[(size_t)r * Dm + c];
    __shared__ float sred[4][Dm];
    sred[g][c] = acc;
    __syncthreads();
    __shared__ float su[2 * Dm];
    __shared__ float sh[Hm];
    if (t < Dm) su[t] = u[b * Dm + t];
    else if (t < 2 * Dm) {
        int cc = t - Dm;
        su[t] = (sred[0][cc] + sred[1][cc] + sred[2][cc] + sred[3][cc]) / cnt;
    }
    __syncthreads();
    if (t < Hm) {
        float h = b1[t];
#pragma unroll 4
        for (int k = 0; k < 2 * Dm; k++) h += su[k] * W1[k * Hm + t];
        sh[t] = fmaxf(h, 0.f);
    }
    __syncthreads();
    if (t < Dm) {
        float o = b2[t];
#pragma unroll 4
        for (int k = 0; k < Hm; k++) o += sh[k] * W2[k * Dm + t];
        u[b * Dm + t] = o;
    }
}

// ---------------- launch -----------------------------------------------------
extern "C" void kernel_launch(void* const* d_in, const int* in_sizes, int n_in,
                              void* d_out, int out_size) {
    const float* node_feats = (const float*)d_in[0];
    const int*   edge_index = (const int*)  d_in[1];
    const float* glob_feats = (const float*)d_in[3];
    const int*   batch      = (const int*)  d_in[4];
    const float* ngam = (const float*)d_in[5];
    const float* nbet = (const float*)d_in[6];
    const float* egam = (const float*)d_in[7];
    const float* ebet = (const float*)d_in[8];
    const float* ggam = (const float*)d_in[9];
    const float* gbet = (const float*)d_in[10];
    const float* eW1 = (const float*)d_in[11];
    const float* eb1 = (const float*)d_in[12];
    const float* eW2 = (const float*)d_in[13];
    const float* eb2 = (const float*)d_in[14];
    const float* nW1 = (const float*)d_in[15];
    const float* nb1 = (const float*)d_in[16];
    const float* nW2 = (const float*)d_in[17];
    const float* nb2 = (const float*)d_in[18];
    const float* gW1 = (const float*)d_in[19];
    const float* gb1 = (const float*)d_in[20];
    const float* gW2 = (const float*)d_in[21];
    const float* gb2 = (const float*)d_in[22];
    const float* edge_feats = (const float*)d_in[2];

    const int N = in_sizes[0] / Dm;
    const int E = in_sizes[2] / Dm;
    const int B = in_sizes[3] / Dm;

    float* x = (float*)d_out;
    float* e = x + (size_t)N * Dm;
    float* u = e + (size_t)E * Dm;
    const int* src = edge_index;
    const int* dst = edge_index + E;

    const int TB = 256;
    int XB = (N * 8 + TB - 1) / TB;
    int gE = (E + TB - 1) / TB;
    int gN = (N + TB - 1) / TB;
    int gTE = (E + TE - 1) / TE;

    cudaFuncSetAttribute(k_edge, cudaFuncAttributeMaxDynamicSharedMemorySize, SMEM_EDGE_BYTES);
    cudaFuncSetAttribute(k_node, cudaFuncAttributeMaxDynamicSharedMemorySize, SMEM_NODE_BYTES);

    // launch 0: BN(x,u) + zero deg
    k_bn_xu<<<XB + 1, TB>>>((const float4*)node_feats, (const float4*)glob_feats,
                            (float4*)x, (float4*)u, ngam, nbet, ggam, gbet, N, B, XB);
    // launch 1: deg count + layer-0 hU
    k_deg_hu<<<gE + 1, TB>>>(dst, u, eW1, eb1, nW1, nb1, ebet, E, B);

    for (int l = 0; l < 3; l++) {
        const float* eW1l = eW1 + (size_t)l * 4 * Dm * Hm;   // (128,64)
        const float* nW1l = nW1 + (size_t)l * 3 * Dm * Hm;   // (96,64)
        const float* gW1l = gW1 + (size_t)l * 2 * Dm * Hm;   // (64,64)
        if (l > 0)
            k_hu<<<1, Hm>>>(u, eW1l, eb1 + l * Hm, nW1l, nb1 + l * Hm, B);
        k_pre<<<gN, TB>>>(x, batch, eW1l, N);                // launch 2 (l=0)
        k_edge<<<gTE, TB, SMEM_EDGE_BYTES>>>(src, dst,       // launch 3 (l=0) — profiled
                           (l == 0) ? edge_feats : e, e,
                           eW1l + 2 * Dm * Hm,               // rows 64..95 (e part)
                           eW2 + (size_t)l * Hm * Dm, eb2 + l * Dm,
                           (l == 0) ? egam : (const float*)nullptr, E);
        k_node<<<gN, TB, SMEM_NODE_BYTES>>>(x, batch, nW1l,
                           nW2 + (size_t)l * Hm * Dm, nb2 + l * Dm, N);
        k_glob<<<B, 128>>>(u, x, batch, gW1l, gb1 + l * Hm,
                           gW2 + (size_t)l * Hm * Dm, gb2 + l * Dm, N);
    }
}

// round 8
// speedup vs baseline: 3.3456x; 1.1335x over previous
#include <cuda_runtime.h>
#include <cstdint>

#define Dm 32
#define Hm 64
#define NMAX 50000
#define BMAX 16
#define TE 256
#define SEIN 260
#define SXT 264
#define SMEM_EDGE_BYTES (64 * 256 * 4)   // sHT overlay dominates; sEinT (33.3KB) aliases it
#define SMEM_NODE_BYTES (64 * SXT * 4)

// ---------------- scratch ----------------------------------------------------
__device__ __align__(16) float g_A  [NMAX * Hm];   // A' = x@W1a + hU[batch]
__device__ __align__(16) float g_Bp [NMAX * Hm];   // B  = x@W1b
__device__ __align__(16) float g_agg[NMAX * Dm];
__device__ __align__(16) float g_hU [BMAX * Hm];
__device__ __align__(16) float g_hUn[BMAX * Hm];
__device__ float g_deg [NMAX];
__device__ float g_rdeg[NMAX];

// ---------------- packed f32x2 helpers ---------------------------------------
static __device__ __forceinline__ uint64_t ffma2(uint64_t a, uint64_t b, uint64_t c) {
    uint64_t d; asm("fma.rn.f32x2 %0, %1, %2, %3;" : "=l"(d) : "l"(a), "l"(b), "l"(c));
    return d;
}
static __device__ __forceinline__ uint64_t pack2(float lo, float hi) {
    uint64_t r; asm("mov.b64 %0, {%1, %2};" : "=l"(r) : "f"(lo), "f"(hi));
    return r;
}
static __device__ __forceinline__ float2 unpack2(uint64_t v) {
    float lo, hi; asm("mov.b64 {%0, %1}, %2;" : "=f"(lo), "=f"(hi) : "l"(v));
    float2 f; f.x = lo; f.y = hi; return f;
}
static __device__ __forceinline__ void red_add_v4(float* p, float a, float b, float c, float d) {
    asm volatile("red.global.add.v4.f32 [%0], {%1, %2, %3, %4};"
                 :: "l"(p), "f"(a), "f"(b), "f"(c), "f"(d) : "memory");
}

// ---------------- launch 0: BN for x and u (+ zero deg) ----------------------
__global__ void k_bn_xu(const float4* __restrict__ nf, const float4* __restrict__ gf,
                        float4* __restrict__ x, float4* __restrict__ u,
                        const float* __restrict__ ngam, const float* __restrict__ nbet,
                        const float* __restrict__ ggam, const float* __restrict__ gbet,
                        int N, int B, int XB) {
    const float r = rsqrtf(1.0f + 1e-5f);
    int bid = blockIdx.x, t = threadIdx.x;
    const float4* in; float4* out; const float* gm; const float* bt; int i4, lim;
    if (bid < XB) { i4 = bid * 256 + t; lim = N * 8; in = nf; out = x; gm = ngam; bt = nbet;
                    if (i4 < N) g_deg[i4] = 0.0f; }
    else          { i4 = t;             lim = B * 8; in = gf; out = u; gm = ggam; bt = gbet; }
    if (i4 >= lim) return;
    float4 v = in[i4];
    int c = (i4 * 4) & (Dm - 1);
    v.x = v.x * (gm[c + 0] * r) + bt[c + 0];
    v.y = v.y * (gm[c + 1] * r) + bt[c + 1];
    v.z = v.z * (gm[c + 2] * r) + bt[c + 2];
    v.w = v.w * (gm[c + 3] * r) + bt[c + 3];
    out[i4] = v;
}

// ---------------- hU/hUn body -------------------------------------------------
static __device__ __forceinline__ void hu_body(
    const float* __restrict__ u,
    const float* __restrict__ eW1, const float* __restrict__ eb1,
    const float* __restrict__ nW1, const float* __restrict__ nb1,
    const float* __restrict__ ebet, int B, int j)
{
    float c = 0.f;
    if (ebet) {            // layer 0: BN shift of e folded through W1c
#pragma unroll 4
        for (int k = 0; k < Dm; k++) c += ebet[k] * eW1[(2 * Dm + k) * Hm + j];
    }
    for (int b = 0; b < B; b++) {
        float hu = eb1[j] + c, hun = nb1[j];
#pragma unroll 4
        for (int k = 0; k < Dm; k++) {
            float uv = u[b * Dm + k];
            hu  += uv * eW1[(3 * Dm + k) * Hm + j];
            hun += uv * nW1[(2 * Dm + k) * Hm + j];
        }
        g_hU [b * Hm + j] = hu;
        g_hUn[b * Hm + j] = hun;
    }
}

// ---------------- launch 1: deg count + layer-0 hU ----------------------------
__global__ void k_deg_hu(const int* __restrict__ dst, const float* __restrict__ u,
                         const float* __restrict__ eW1, const float* __restrict__ eb1,
                         const float* __restrict__ nW1, const float* __restrict__ nb1,
                         const float* __restrict__ ebet, int E, int B) {
    if (blockIdx.x == gridDim.x - 1) {
        if (threadIdx.x < Hm) hu_body(u, eW1, eb1, nW1, nb1, ebet, B, threadIdx.x);
        return;
    }
    int i = blockIdx.x * blockDim.x + threadIdx.x;
    if (i < E) atomicAdd(&g_deg[dst[i]], 1.0f);
}

// layers 1,2: standalone hU
__global__ void k_hu(const float* __restrict__ u,
                     const float* __restrict__ eW1, const float* __restrict__ eb1,
                     const float* __restrict__ nW1, const float* __restrict__ nb1, int B) {
    if (threadIdx.x < Hm) hu_body(u, eW1, eb1, nW1, nb1, nullptr, B, threadIdx.x);
}

// ---------------- per-layer: A'/B precompute (tiled GEMM) + rdeg + zero agg ---
__global__ void __launch_bounds__(256, 2) k_pre(const float* __restrict__ x,
                                                const int* __restrict__ batch,
                                                const float* __restrict__ eW1, int N) {
    __shared__ __align__(16) float sX[32 * SXT];
    __shared__ int sBt[256];
    int t = threadIdx.x;
    int n0 = blockIdx.x * 256;
    int ng = min(n0 + t, N - 1);
    sBt[t] = batch[ng];
    if (n0 + t < N) g_rdeg[n0 + t] = 1.0f / fmaxf(g_deg[n0 + t], 1.0f);
    {   // zero this block's agg region
        float4 z = make_float4(0.f, 0.f, 0.f, 0.f);
        float4* pz = (float4*)(g_agg + (size_t)n0 * Dm);
        int lim4 = min(256, N - n0) * 8;
        for (int i = t; i < lim4; i += 256) pz[i] = z;
    }
    {   // stage x^T, quad swizzle
        int l8 = t & 7, g8 = t >> 3, k0 = l8 * 4;
#pragma unroll 2
        for (int p = 0; p < 8; p++) {
            int nL = p * 32 + g8;
            int ngl = min(n0 + nL, N - 1);
            float4 v = __ldg((const float4*)(x + (size_t)ngl * Dm) + l8);
            int col = (((nL >> 2) ^ l8) << 2) + (nL & 3);
            sX[(k0 + 0) * SXT + col] = v.x;
            sX[(k0 + 1) * SXT + col] = v.y;
            sX[(k0 + 2) * SXT + col] = v.z;
            sX[(k0 + 3) * SXT + col] = v.w;
        }
    }
    __syncthreads();

    int jb = t & 7, nbk = t >> 3;
    uint64_t acc[8][4];
#pragma unroll
    for (int g = 0; g < 2; g++) {               // g=0: A' (rows 0..31, hU bias); g=1: B (rows 32..63)
        const float* W = eW1 + g * Dm * Hm;
        float* O = g ? g_Bp : g_A;
#pragma unroll
        for (int i = 0; i < 8; i++) {
            if (g == 0) {
                int bb = sBt[nbk * 8 + i];
                const ulonglong2* pb = (const ulonglong2*)(g_hU + bb * Hm + jb * 8);
                ulonglong2 b0 = __ldg(pb), b1 = __ldg(pb + 1);
                acc[i][0] = b0.x; acc[i][1] = b0.y; acc[i][2] = b1.x; acc[i][3] = b1.y;
            } else {
                acc[i][0] = acc[i][1] = acc[i][2] = acc[i][3] = 0ull;
            }
        }
#pragma unroll 4
        for (int k = 0; k < Dm; k++) {
            int sw = k >> 2;
            const float4* pe = (const float4*)(sX + k * SXT);
            float4 ea = pe[(nbk * 2) ^ sw];
            float4 eb = pe[(nbk * 2 + 1) ^ sw];
            ulonglong2 wA = __ldg((const ulonglong2*)(W + k * Hm + jb * 8));
            ulonglong2 wB = __ldg((const ulonglong2*)(W + k * Hm + jb * 8 + 4));
            float ev[8] = {ea.x, ea.y, ea.z, ea.w, eb.x, eb.y, eb.z, eb.w};
#pragma unroll
            for (int i = 0; i < 8; i++) {
                uint64_t ed = pack2(ev[i], ev[i]);
                acc[i][0] = ffma2(ed, wA.x, acc[i][0]);
                acc[i][1] = ffma2(ed, wA.y, acc[i][1]);
                acc[i][2] = ffma2(ed, wB.x, acc[i][2]);
                acc[i][3] = ffma2(ed, wB.y, acc[i][3]);
            }
        }
#pragma unroll
        for (int i = 0; i < 8; i++) {
            int n = n0 + nbk * 8 + i;
            if (n < N) {
                float2 a0 = unpack2(acc[i][0]), a1 = unpack2(acc[i][1]);
                float2 a2 = unpack2(acc[i][2]), a3 = unpack2(acc[i][3]);
                *(float4*)(O + (size_t)n * Hm + jb * 8)     = make_float4(a0.x, a0.y, a1.x, a1.y);
                *(float4*)(O + (size_t)n * Hm + jb * 8 + 4) = make_float4(a2.x, a2.y, a3.x, a3.y);
            }
        }
    }
}

// ---------------- per-layer: edge MLP — register-tiled block GEMMs -----------
// R8: direct bias init (no smem staging of A'+B); sHT overlays sEinT.
__global__ void __launch_bounds__(256, 2) k_edge(
    const int* __restrict__ src, const int* __restrict__ dst,
    const float* __restrict__ ein, float* __restrict__ eout,
    const float* __restrict__ W1c, const float* __restrict__ W2,
    const float* __restrict__ b2, const float* __restrict__ escale, int E)
{
    extern __shared__ float smem[];
    float* sEinT = smem;                  // [32][260], alive until end of GEMM1
    float* sHT   = smem;                  // [64][256] overlay, after sync
    __shared__ int sS[TE], sD[TE];
    __shared__ float sSc[Dm];
    int t = threadIdx.x;
    int e0 = blockIdx.x * TE;

    if (t < Dm) sSc[t] = escale ? escale[t] * rsqrtf(1.0f + 1e-5f) : 1.0f;
    int ei = min(e0 + t, E - 1);
    sS[t] = src[ei]; sD[t] = dst[ei];
    __syncthreads();

    // ---- stage Ein transposed, quad swizzle, BN scale fold ----
    {
        int l8 = t & 7, g8 = t >> 3;
        int k0 = l8 * 4;
        float s0 = sSc[k0], s1 = sSc[k0 + 1], s2 = sSc[k0 + 2], s3 = sSc[k0 + 3];
#pragma unroll 2
        for (int p = 0; p < 8; p++) {
            int eL = p * 32 + g8;
            int eg = min(e0 + eL, E - 1);
            float4 v = __ldg((const float4*)(ein + (size_t)eg * Dm) + l8);
            int col = (((eL >> 2) ^ l8) << 2) + (eL & 3);
            sEinT[(k0 + 0) * SEIN + col] = v.x * s0;
            sEinT[(k0 + 1) * SEIN + col] = v.y * s1;
            sEinT[(k0 + 2) * SEIN + col] = v.z * s2;
            sEinT[(k0 + 3) * SEIN + col] = v.w * s3;
        }
    }

    // ---- direct bias init: acc = A'[src] + B[dst] (jb slice, 8 edges) ----
    int jb = t & 7, ebk = t >> 3;
    uint64_t acc[8][4];
#pragma unroll
    for (int i = 0; i < 8; i++) {
        int eL = ebk * 8 + i;
        const float4* pa = (const float4*)(g_A  + (size_t)sS[eL] * Hm + jb * 8);
        const float4* pb = (const float4*)(g_Bp + (size_t)sD[eL] * Hm + jb * 8);
        float4 a0 = __ldg(pa), a1 = __ldg(pa + 1);
        float4 b0 = __ldg(pb), b1 = __ldg(pb + 1);
        acc[i][0] = pack2(a0.x + b0.x, a0.y + b0.y);
        acc[i][1] = pack2(a0.z + b0.z, a0.w + b0.w);
        acc[i][2] = pack2(a1.x + b1.x, a1.y + b1.y);
        acc[i][3] = pack2(a1.z + b1.z, a1.w + b1.w);
    }
    __syncthreads();   // sEinT staged

    // ---- GEMM1: H[256x64] = EinT^T @ W1c + bias ----
#pragma unroll 4
    for (int k = 0; k < Dm; k++) {
        int sw = k >> 2;
        const float4* pe = (const float4*)(sEinT + k * SEIN);
        float4 ea = pe[(ebk * 2) ^ sw];
        float4 eb = pe[(ebk * 2 + 1) ^ sw];
        ulonglong2 wA = __ldg((const ulonglong2*)(W1c + k * Hm + jb * 8));
        ulonglong2 wB = __ldg((const ulonglong2*)(W1c + k * Hm + jb * 8 + 4));
        float ev[8] = {ea.x, ea.y, ea.z, ea.w, eb.x, eb.y, eb.z, eb.w};
#pragma unroll
        for (int i = 0; i < 8; i++) {
            uint64_t ed = pack2(ev[i], ev[i]);
            acc[i][0] = ffma2(ed, wA.x, acc[i][0]);
            acc[i][1] = ffma2(ed, wA.y, acc[i][1]);
            acc[i][2] = ffma2(ed, wB.x, acc[i][2]);
            acc[i][3] = ffma2(ed, wB.y, acc[i][3]);
        }
    }
    __syncthreads();   // sEinT dead; safe to overlay sHT

    // ---- relu + store H^T [64][256], quad swizzle q ^ jb ----
#pragma unroll
    for (int jj = 0; jj < 8; jj++) {
        int j = jb * 8 + jj;
        float f[8];
#pragma unroll
        for (int i = 0; i < 8; i++) {
            float2 v = unpack2(acc[i][jj >> 1]);
            f[i] = fmaxf((jj & 1) ? v.y : v.x, 0.f);
        }
        *(float4*)(sHT + j * 256 + (((ebk * 2)     ^ jb) << 2)) = make_float4(f[0], f[1], f[2], f[3]);
        *(float4*)(sHT + j * 256 + (((ebk * 2 + 1) ^ jb) << 2)) = make_float4(f[4], f[5], f[6], f[7]);
    }
    __syncthreads();

    // ---- GEMM2: OUT[256x32] = relu(H) @ W2 + b2 ----
    uint64_t out[8][2];
    {
        ulonglong2 bb = __ldg((const ulonglong2*)(b2 + jb * 4));
#pragma unroll
        for (int i = 0; i < 8; i++) { out[i][0] = bb.x; out[i][1] = bb.y; }
    }
#pragma unroll 4
    for (int k = 0; k < Hm; k++) {
        int sw = (k >> 3) & 7;
        const float4* ph = (const float4*)(sHT + k * 256);
        float4 h0 = ph[(ebk * 2) ^ sw];
        float4 h1 = ph[(ebk * 2 + 1) ^ sw];
        ulonglong2 w = __ldg((const ulonglong2*)(W2 + k * Dm + jb * 4));
        float hv[8] = {h0.x, h0.y, h0.z, h0.w, h1.x, h1.y, h1.z, h1.w};
#pragma unroll
        for (int i = 0; i < 8; i++) {
            uint64_t hd = pack2(hv[i], hv[i]);
            out[i][0] = ffma2(hd, w.x, out[i][0]);
            out[i][1] = ffma2(hd, w.y, out[i][1]);
        }
    }
    // ---- epilogue: write e + fused RED into agg ----
#pragma unroll
    for (int i = 0; i < 8; i++) {
        int eL = ebk * 8 + i, eg = e0 + eL;
        if (eg < E) {
            float2 a = unpack2(out[i][0]); float2 b = unpack2(out[i][1]);
            *(float4*)(eout + (size_t)eg * Dm + jb * 4) = make_float4(a.x, a.y, b.x, b.y);
            red_add_v4(g_agg + (size_t)sD[eL] * Dm + jb * 4, a.x, a.y, b.x, b.y);
        }
    }
}

// ---------------- per-layer: node MLP — register-tiled block GEMMs -----------
__global__ void __launch_bounds__(256, 2) k_node(
    float* __restrict__ x, const int* __restrict__ batch,
    const float* __restrict__ W1, const float* __restrict__ W2, const float* __restrict__ b2,
    int N)
{
    extern __shared__ float smem[];
    float* sIn = smem;     // [64][264]: rows 0..31 = x^T, rows 32..63 = (agg*rd)^T
    float* sHT = smem;     // overlay after GEMM1: [64][256]
    __shared__ int sBt[256];
    int t = threadIdx.x;
    int n0 = blockIdx.x * 256;
    sBt[t] = batch[min(n0 + t, N - 1)];
    {
        int l8 = t & 7, g8 = t >> 3, k0 = l8 * 4;
#pragma unroll 2
        for (int p = 0; p < 8; p++) {
            int nL = p * 32 + g8;
            int ngl = min(n0 + nL, N - 1);
            float4 vx = __ldg((const float4*)(x + (size_t)ngl * Dm) + l8);
            float rd = g_rdeg[ngl];
            float4 va = __ldg((const float4*)(g_agg + (size_t)ngl * Dm) + l8);
            int col = (((nL >> 2) ^ l8) << 2) + (nL & 3);
            sIn[(k0 + 0) * SXT + col] = vx.x;
            sIn[(k0 + 1) * SXT + col] = vx.y;
            sIn[(k0 + 2) * SXT + col] = vx.z;
            sIn[(k0 + 3) * SXT + col] = vx.w;
            sIn[(Dm + k0 + 0) * SXT + col] = va.x * rd;
            sIn[(Dm + k0 + 1) * SXT + col] = va.y * rd;
            sIn[(Dm + k0 + 2) * SXT + col] = va.z * rd;
            sIn[(Dm + k0 + 3) * SXT + col] = va.w * rd;
        }
    }
    __syncthreads();

    // ---- GEMM1: H[256x64] = In^T @ W1(rows 0..63) + hUn[batch] ----
    int jb = t & 7, nbk = t >> 3;
    uint64_t acc[8][4];
#pragma unroll
    for (int i = 0; i < 8; i++) {
        int bb = sBt[nbk * 8 + i];
        const ulonglong2* pb = (const ulonglong2*)(g_hUn + bb * Hm + jb * 8);
        ulonglong2 b0 = __ldg(pb), b1 = __ldg(pb + 1);
        acc[i][0] = b0.x; acc[i][1] = b0.y; acc[i][2] = b1.x; acc[i][3] = b1.y;
    }
#pragma unroll 4
    for (int k = 0; k < 2 * Dm; k++) {
        int sw = (k >> 2) & 7;
        const float4* pe = (const float4*)(sIn + k * SXT);
        float4 ea = pe[(nbk * 2) ^ sw];
        float4 eb = pe[(nbk * 2 + 1) ^ sw];
        ulonglong2 wA = __ldg((const ulonglong2*)(W1 + k * Hm + jb * 8));
        ulonglong2 wB = __ldg((const ulonglong2*)(W1 + k * Hm + jb * 8 + 4));
        float ev[8] = {ea.x, ea.y, ea.z, ea.w, eb.x, eb.y, eb.z, eb.w};
#pragma unroll
        for (int i = 0; i < 8; i++) {
            uint64_t ed = pack2(ev[i], ev[i]);
            acc[i][0] = ffma2(ed, wA.x, acc[i][0]);
            acc[i][1] = ffma2(ed, wA.y, acc[i][1]);
            acc[i][2] = ffma2(ed, wB.x, acc[i][2]);
            acc[i][3] = ffma2(ed, wB.y, acc[i][3]);
        }
    }
    __syncthreads();   // all reads of sIn complete before HT overlay

#pragma unroll
    for (int jj = 0; jj < 8; jj++) {
        int j = jb * 8 + jj;
        float f[8];
#pragma unroll
        for (int i = 0; i < 8; i++) {
            float2 v = unpack2(acc[i][jj >> 1]);
            f[i] = fmaxf((jj & 1) ? v.y : v.x, 0.f);
        }
        *(float4*)(sHT + j * 256 + (((nbk * 2)     ^ jb) << 2)) = make_float4(f[0], f[1], f[2], f[3]);
        *(float4*)(sHT + j * 256 + (((nbk * 2 + 1) ^ jb) << 2)) = make_float4(f[4], f[5], f[6], f[7]);
    }
    __syncthreads();

    // ---- GEMM2: OUT[256x32] = relu(H) @ W2 + b2 ----
    uint64_t out[8][2];
    {
        ulonglong2 bb = __ldg((const ulonglong2*)(b2 + jb * 4));
#pragma unroll
        for (int i = 0; i < 8; i++) { out[i][0] = bb.x; out[i][1] = bb.y; }
    }
#pragma unroll 4
    for (int k = 0; k < Hm; k++) {
        int sw = (k >> 3) & 7;
        const float4* ph = (const float4*)(sHT + k * 256);
        float4 h0 = ph[(nbk * 2) ^ sw];
        float4 h1 = ph[(nbk * 2 + 1) ^ sw];
        ulonglong2 w = __ldg((const ulonglong2*)(W2 + k * Dm + jb * 4));
        float hv[8] = {h0.x, h0.y, h0.z, h0.w, h1.x, h1.y, h1.z, h1.w};
#pragma unroll
        for (int i = 0; i < 8; i++) {
            uint64_t hd = pack2(hv[i], hv[i]);
            out[i][0] = ffma2(hd, w.x, out[i][0]);
            out[i][1] = ffma2(hd, w.y, out[i][1]);
        }
    }
#pragma unroll
    for (int i = 0; i < 8; i++) {
        int n = n0 + nbk * 8 + i;
        if (n < N) {
            float2 a = unpack2(out[i][0]); float2 b = unpack2(out[i][1]);
            *(float4*)(x + (size_t)n * Dm + jb * 4) = make_float4(a.x, a.y, b.x, b.y);
        }
    }
}

// ---------------- per-layer: global MLP (sorted-batch segment reduce) --------
static __device__ __forceinline__ int lowerb(const int* __restrict__ a, int n, int v) {
    int lo = 0, hi = n;
    while (lo < hi) { int m = (lo + hi) >> 1; if (a[m] < v) lo = m + 1; else hi = m; }
    return lo;
}
__global__ void k_glob(float* __restrict__ u, const float* __restrict__ x,
                       const int* __restrict__ batch,
                       const float* __restrict__ W1, const float* __restrict__ b1,
                       const float* __restrict__ W2, const float* __restrict__ b2, int N) {
    int b = blockIdx.x, t = threadIdx.x;       // 128 threads
    __shared__ int sLo, sHi;
    if (t == 0) { sLo = lowerb(batch, N, b); sHi = lowerb(batch, N, b + 1); }
    __syncthreads();
    int lo = sLo, hi = sHi;
    float cnt = fmaxf((float)(hi - lo), 1.0f);
    int c = t & 31, g = t >> 5;
    float acc = 0.f;
    for (int r = lo + g; r < hi; r += 4) acc += x[(size_t)r * Dm + c];
    __shared__ float sred[4][Dm];
    sred[g][c] = acc;
    __syncthreads();
    __shared__ float su[2 * Dm];
    __shared__ float sh[Hm];
    if (t < Dm) su[t] = u[b * Dm + t];
    else if (t < 2 * Dm) {
        int cc = t - Dm;
        su[t] = (sred[0][cc] + sred[1][cc] + sred[2][cc] + sred[3][cc]) / cnt;
    }
    __syncthreads();
    if (t < Hm) {
        float h = b1[t];
#pragma unroll 4
        for (int k = 0; k < 2 * Dm; k++) h += su[k] * W1[k * Hm + t];
        sh[t] = fmaxf(h, 0.f);
    }
    __syncthreads();
    if (t < Dm) {
        float o = b2[t];
#pragma unroll 4
        for (int k = 0; k < Hm; k++) o += sh[k] * W2[k * Dm + t];
        u[b * Dm + t] = o;
    }
}

// ---------------- launch -----------------------------------------------------
extern "C" void kernel_launch(void* const* d_in, const int* in_sizes, int n_in,
                              void* d_out, int out_size) {
    const float* node_feats = (const float*)d_in[0];
    const int*   edge_index = (const int*)  d_in[1];
    const float* edge_feats = (const float*)d_in[2];
    const float* glob_feats = (const float*)d_in[3];
    const int*   batch      = (const int*)  d_in[4];
    const float* ngam = (const float*)d_in[5];
    const float* nbet = (const float*)d_in[6];
    const float* egam = (const float*)d_in[7];
    const float* ebet = (const float*)d_in[8];
    const float* ggam = (const float*)d_in[9];
    const float* gbet = (const float*)d_in[10];
    const float* eW1 = (const float*)d_in[11];
    const float* eb1 = (const float*)d_in[12];
    const float* eW2 = (const float*)d_in[13];
    const float* eb2 = (const float*)d_in[14];
    const float* nW1 = (const float*)d_in[15];
    const float* nb1 = (const float*)d_in[16];
    const float* nW2 = (const float*)d_in[17];
    const float* nb2 = (const float*)d_in[18];
    const float* gW1 = (const float*)d_in[19];
    const float* gb1 = (const float*)d_in[20];
    const float* gW2 = (const float*)d_in[21];
    const float* gb2 = (const float*)d_in[22];

    const int N = in_sizes[0] / Dm;
    const int E = in_sizes[2] / Dm;
    const int B = in_sizes[3] / Dm;

    float* x = (float*)d_out;
    float* e = x + (size_t)N * Dm;
    float* u = e + (size_t)E * Dm;
    const int* src = edge_index;
    const int* dst = edge_index + E;

    const int TB = 256;
    int XB = (N * 8 + TB - 1) / TB;
    int gE = (E + TB - 1) / TB;
    int gN = (N + TB - 1) / TB;
    int gTE = (E + TE - 1) / TE;

    cudaFuncSetAttribute(k_edge, cudaFuncAttributeMaxDynamicSharedMemorySize, SMEM_EDGE_BYTES);
    cudaFuncSetAttribute(k_node, cudaFuncAttributeMaxDynamicSharedMemorySize, SMEM_NODE_BYTES);

    // launch 0: BN(x,u) + zero deg
    k_bn_xu<<<XB + 1, TB>>>((const float4*)node_feats, (const float4*)glob_feats,
                            (float4*)x, (float4*)u, ngam, nbet, ggam, gbet, N, B, XB);
    // launch 1: deg count + layer-0 hU
    k_deg_hu<<<gE + 1, TB>>>(dst, u, eW1, eb1, nW1, nb1, ebet, E, B);

    for (int l = 0; l < 3; l++) {
        const float* eW1l = eW1 + (size_t)l * 4 * Dm * Hm;   // (128,64)
        const float* nW1l = nW1 + (size_t)l * 3 * Dm * Hm;   // (96,64)
        const float* gW1l = gW1 + (size_t)l * 2 * Dm * Hm;   // (64,64)
        if (l > 0)
            k_hu<<<1, Hm>>>(u, eW1l, eb1 + l * Hm, nW1l, nb1 + l * Hm, B);
        k_pre<<<gN, TB>>>(x, batch, eW1l, N);                // launch 2 (l=0)
        k_edge<<<gTE, TB, SMEM_EDGE_BYTES>>>(src, dst,       // launch 3 (l=0) — profiled
                           (l == 0) ? edge_feats : e, e,
                           eW1l + 2 * Dm * Hm,               // rows 64..95 (e part)
                           eW2 + (size_t)l * Hm * Dm, eb2 + l * Dm,
                           (l == 0) ? egam : (const float*)nullptr, E);
        k_node<<<gN, TB, SMEM_NODE_BYTES>>>(x, batch, nW1l,
                           nW2 + (size_t)l * Hm * Dm, nb2 + l * Dm, N);
        k_glob<<<B, 128>>>(u, x, batch, gW1l, gb1 + l * Hm,
                           gW2 + (size_t)l * Hm * Dm, gb2 + l * Dm, N);
    }
}